// round 6
// baseline (speedup 1.0000x reference)
#include <cuda_runtime.h>
#include <cuda_bf16.h>
#include <math.h>
#include <stdint.h>

#define BSZ 1024
#define LL  128
#define EE  256
#define HH  512
#define TT  20
#define G4  (4*HH)    // 2048
#define XW  (EE+HH)   // 768
#define VMAX 1024

// ---------------- persistent scratch ----------------------------------------
__device__ float g_C[BSZ*HH];
__device__ float g_PQ[BSZ*EE];
__device__ float g_GATT[BSZ*G4];
__device__ float g_WqT[HH*EE];
__device__ float g_WihT[EE*G4];
__device__ float g_WcT[XW*HH];
__device__ float g_WhhT[HH*G4];
__device__ float g_Wcomb[XW*G4];
__device__ float g_ProjEmb[VMAX*G4];
__device__ float g_BiasC[G4];
__device__ __nv_bfloat16 g_Xhi[BSZ*XW];    // [applied | h] split-bf16
__device__ __nv_bfloat16 g_Xlo[BSZ*XW];
__device__ __nv_bfloat16 g_Whi[XW*G4];     // Wcomb split, [K,N]
__device__ __nv_bfloat16 g_Wlo[XW*G4];
__device__ __nv_bfloat16 g_WqThi[HH*EE];   // WqT split
__device__ __nv_bfloat16 g_WqTlo[HH*EE];

__device__ __forceinline__ uint32_t smem_u32(const void* p) {
    return (uint32_t)__cvta_generic_to_shared(p);
}
#define CP16(dst, src) asm volatile("cp.async.cg.shared.global [%0], [%1], 16;\n" :: "r"(dst), "l"(src))

// ---------------- transpose --------------------------------------------------
__global__ void transpose_k(const float* __restrict__ in, float* __restrict__ out,
                            int rows, int cols)
{
    __shared__ float tile[32][33];
    int x0 = blockIdx.x * 32, y0 = blockIdx.y * 32;
    int tx = threadIdx.x;
    for (int j = threadIdx.y; j < 32; j += 8) {
        int r = y0 + j, c = x0 + tx;
        if (r < rows && c < cols) tile[j][tx] = in[(size_t)r * cols + c];
    }
    __syncthreads();
    for (int j = threadIdx.y; j < 32; j += 8) {
        int orow = x0 + j, ocol = y0 + tx;
        if (orow < cols && ocol < rows) out[(size_t)orow * rows + ocol] = tile[tx][j];
    }
}

// ---------------- fp32 tiled GEMM (setup only) -------------------------------
__global__ __launch_bounds__(256) void gemm_k(
    const float* __restrict__ A, const float* __restrict__ B,
    float* __restrict__ C, const float* __restrict__ bias,
    int M, int N, int K, int lda, int ldb, int ldc)
{
    __shared__ float As[16][68];
    __shared__ float Bs[16][68];
    const int tid = threadIdx.x;
    const int tx  = tid & 15, ty = tid >> 4;
    const int bm  = blockIdx.y << 6, bn = blockIdx.x << 6;
    const int arow = tid >> 2, ak = (tid & 3) << 2;
    const int brow = tid >> 4, bcol = (tid & 15) << 2;

    float acc[4][4];
    #pragma unroll
    for (int i = 0; i < 4; i++)
        #pragma unroll
        for (int j = 0; j < 4; j++) acc[i][j] = 0.f;

    const bool aval = (bm + arow) < M;
    const float* Aptr = A + (size_t)(bm + arow) * lda + ak;
    const float* Bptr = B + (size_t)brow * ldb + bn + bcol;

    for (int k0 = 0; k0 < K; k0 += 16) {
        float4 av = aval ? *(const float4*)(Aptr + k0)
                         : make_float4(0.f, 0.f, 0.f, 0.f);
        As[ak + 0][arow] = av.x; As[ak + 1][arow] = av.y;
        As[ak + 2][arow] = av.z; As[ak + 3][arow] = av.w;
        float4 bv = *(const float4*)(Bptr + (size_t)k0 * ldb);
        *(float4*)(&Bs[brow][bcol]) = bv;
        __syncthreads();
        #pragma unroll
        for (int k = 0; k < 16; k++) {
            float4 a = *(const float4*)(&As[k][ty << 2]);
            float4 b = *(const float4*)(&Bs[k][tx << 2]);
            acc[0][0] += a.x * b.x; acc[0][1] += a.x * b.y; acc[0][2] += a.x * b.z; acc[0][3] += a.x * b.w;
            acc[1][0] += a.y * b.x; acc[1][1] += a.y * b.y; acc[1][2] += a.y * b.z; acc[1][3] += a.y * b.w;
            acc[2][0] += a.z * b.x; acc[2][1] += a.z * b.y; acc[2][2] += a.z * b.z; acc[2][3] += a.z * b.w;
            acc[3][0] += a.w * b.x; acc[3][1] += a.w * b.y; acc[3][2] += a.w * b.z; acc[3][3] += a.w * b.w;
        }
        __syncthreads();
    }

    float4 bb = bias ? *(const float4*)(bias + bn + (tx << 2))
                     : make_float4(0.f, 0.f, 0.f, 0.f);
    #pragma unroll
    for (int i = 0; i < 4; i++) {
        int row = bm + (ty << 2) + i;
        if (row < M) {
            float4 o;
            o.x = acc[i][0] + bb.x; o.y = acc[i][1] + bb.y;
            o.z = acc[i][2] + bb.z; o.w = acc[i][3] + bb.w;
            *(float4*)(C + (size_t)row * ldc + bn + (tx << 2)) = o;
        }
    }
}

// ---------------- MMA helpers --------------------------------------------------
__device__ __forceinline__ void ldsm_x4(uint32_t r[4], uint32_t addr) {
    asm volatile("ldmatrix.sync.aligned.m8n8.x4.shared.b16 {%0,%1,%2,%3}, [%4];\n"
        : "=r"(r[0]), "=r"(r[1]), "=r"(r[2]), "=r"(r[3]) : "r"(addr));
}
__device__ __forceinline__ void ldsm_x2t(uint32_t r[2], uint32_t addr) {
    asm volatile("ldmatrix.sync.aligned.m8n8.x2.trans.shared.b16 {%0,%1}, [%2];\n"
        : "=r"(r[0]), "=r"(r[1]) : "r"(addr));
}
__device__ __forceinline__ void mma16816(float* c, const uint32_t a[4], const uint32_t b[2]) {
    asm volatile(
        "mma.sync.aligned.m16n8k16.row.col.f32.bf16.bf16.f32 "
        "{%0,%1,%2,%3}, {%4,%5,%6,%7}, {%8,%9}, {%0,%1,%2,%3};\n"
        : "+f"(c[0]), "+f"(c[1]), "+f"(c[2]), "+f"(c[3])
        : "r"(a[0]), "r"(a[1]), "r"(a[2]), "r"(a[3]), "r"(b[0]), "r"(b[1]));
}

// ---------------- gates GEMM: 128x64 tile, 4 warps, 2-3 CTAs/SM ---------------
// C[M,N] = (Ahi+Alo)[M,K] @ (Bhi+Blo)[K,N], 3 passes, fp32 accum.
#define GT_SA 40
#define GT_SB 72
#define GT_BM 128
#define GT_BN 64
#define GT_BK 32
#define GT_ASZ (GT_BM*GT_SA)            // 5120
#define GT_BSZ (GT_BK*GT_SB)            // 2304
#define GT_STG (2*GT_ASZ + 2*GT_BSZ)    // 14848 elems
#define GT_SMEM (2*GT_STG*2)            // 59392 B

__global__ __launch_bounds__(128) void mma_gates_k(
    const __nv_bfloat16* __restrict__ Ahi, const __nv_bfloat16* __restrict__ Alo,
    const __nv_bfloat16* __restrict__ Bhi, const __nv_bfloat16* __restrict__ Blo,
    float* __restrict__ C, int lda, int ldb, int ldc)
{
    extern __shared__ __nv_bfloat16 smg[];
    __nv_bfloat16* stg[2] = { smg, smg + GT_STG };

    const int tid  = threadIdx.x;
    const int lane = tid & 31, warp = tid >> 5;
    const int bm = blockIdx.y * GT_BM, bn = blockIdx.x * GT_BN;
    const int wm = (warp >> 1) * 64, wn = (warp & 1) * 32;

    float acc[4][4][4];
    #pragma unroll
    for (int i = 0; i < 4; i++)
        #pragma unroll
        for (int j = 0; j < 4; j++)
            #pragma unroll
            for (int l = 0; l < 4; l++) acc[i][j][l] = 0.f;

    auto issue_loads = [&](int s, int k0) {
        __nv_bfloat16* sAhi = stg[s];
        __nv_bfloat16* sAlo = stg[s] + GT_ASZ;
        __nv_bfloat16* sBhi = stg[s] + 2 * GT_ASZ;
        __nv_bfloat16* sBlo = stg[s] + 2 * GT_ASZ + GT_BSZ;
        #pragma unroll
        for (int i = 0; i < 4; i++) {   // A: 512 chunks over 128 threads
            int ai = tid * 4 + i, ar = ai >> 2, ac = (ai & 3) * 8;
            CP16(smem_u32(sAhi + ar * GT_SA + ac), Ahi + (size_t)(bm + ar) * lda + k0 + ac);
            CP16(smem_u32(sAlo + ar * GT_SA + ac), Alo + (size_t)(bm + ar) * lda + k0 + ac);
        }
        #pragma unroll
        for (int i = 0; i < 2; i++) {   // B: 256 chunks over 128 threads
            int bi = tid * 2 + i, br = bi >> 3, bc = (bi & 7) * 8;
            CP16(smem_u32(sBhi + br * GT_SB + bc), Bhi + (size_t)(k0 + br) * ldb + bn + bc);
            CP16(smem_u32(sBlo + br * GT_SB + bc), Blo + (size_t)(k0 + br) * ldb + bn + bc);
        }
        asm volatile("cp.async.commit_group;\n");
    };

    const int niter = XW / GT_BK;  // 24
    issue_loads(0, 0);

    const int a_ro = (lane & 7) + ((lane >> 3) & 1) * 8;
    const int a_ko = ((lane >> 4) & 1) * 8;
    const int b_ro = (lane & 7) + ((lane >> 3) & 1) * 8;

    for (int it = 0; it < niter; it++) {
        int s = it & 1;
        if (it + 1 < niter) { issue_loads(s ^ 1, (it + 1) * GT_BK);
                              asm volatile("cp.async.wait_group 1;\n"); }
        else                  asm volatile("cp.async.wait_group 0;\n");
        __syncthreads();

        const __nv_bfloat16* sAhi = stg[s];
        const __nv_bfloat16* sAlo = stg[s] + GT_ASZ;
        const __nv_bfloat16* sBhi = stg[s] + 2 * GT_ASZ;
        const __nv_bfloat16* sBlo = stg[s] + 2 * GT_ASZ + GT_BSZ;

        #pragma unroll
        for (int ks = 0; ks < GT_BK; ks += 16) {
            uint32_t bh[4][2], bl[4][2];
            #pragma unroll
            for (int nf = 0; nf < 4; nf++) {
                ldsm_x2t(bh[nf], smem_u32(sBhi + (ks + b_ro) * GT_SB + wn + nf * 8));
                ldsm_x2t(bl[nf], smem_u32(sBlo + (ks + b_ro) * GT_SB + wn + nf * 8));
            }
            #pragma unroll
            for (int mf = 0; mf < 4; mf++) {
                uint32_t ah[4], al[4];
                int arow = wm + mf * 16 + a_ro;
                ldsm_x4(ah, smem_u32(sAhi + arow * GT_SA + ks + a_ko));
                ldsm_x4(al, smem_u32(sAlo + arow * GT_SA + ks + a_ko));
                #pragma unroll
                for (int nf = 0; nf < 4; nf++) {
                    mma16816(acc[mf][nf], ah, bh[nf]);
                    mma16816(acc[mf][nf], ah, bl[nf]);
                    mma16816(acc[mf][nf], al, bh[nf]);
                }
            }
        }
        __syncthreads();
    }

    #pragma unroll
    for (int mf = 0; mf < 4; mf++) {
        int row0 = bm + wm + mf * 16 + (lane >> 2);
        #pragma unroll
        for (int nf = 0; nf < 4; nf++) {
            int col = bn + wn + nf * 8 + (lane & 3) * 2;
            *(float2*)(C + (size_t)row0 * ldc + col) =
                make_float2(acc[mf][nf][0], acc[mf][nf][1]);
            *(float2*)(C + (size_t)(row0 + 8) * ldc + col) =
                make_float2(acc[mf][nf][2], acc[mf][nf][3]);
        }
    }
}

// ---------------- split-bf16 pq GEMM (64x64x32, 128 thr) ----------------------
#define P_SA 40
#define P_SB 72
#define P_BM 64
#define P_BN 64
#define P_BK 32
#define P_ASZ (P_BM*P_SA)
#define P_BSZ (P_BK*P_SB)
#define P_STG (2*P_ASZ + 2*P_BSZ)
#define P_SMEM (2*P_STG*2)

__global__ __launch_bounds__(128) void mma_pq_k(
    const __nv_bfloat16* __restrict__ Ahi, const __nv_bfloat16* __restrict__ Alo,
    const __nv_bfloat16* __restrict__ Bhi, const __nv_bfloat16* __restrict__ Blo,
    float* __restrict__ C, const float* __restrict__ bias,
    int M, int N, int K, int lda, int ldb, int ldc)
{
    extern __shared__ __nv_bfloat16 smb[];
    __nv_bfloat16* stg[2] = { smb, smb + P_STG };

    const int tid  = threadIdx.x;
    const int lane = tid & 31, warp = tid >> 5;
    const int bm = blockIdx.y * P_BM, bn = blockIdx.x * P_BN;
    const int wm = (warp >> 1) * 32, wn = (warp & 1) * 32;

    float acc[2][4][4];
    #pragma unroll
    for (int i = 0; i < 2; i++)
        #pragma unroll
        for (int j = 0; j < 4; j++)
            #pragma unroll
            for (int l = 0; l < 4; l++) acc[i][j][l] = 0.f;

    auto issue_loads = [&](int s, int k0) {
        __nv_bfloat16* sAhi = stg[s];
        __nv_bfloat16* sAlo = stg[s] + P_ASZ;
        __nv_bfloat16* sBhi = stg[s] + 2 * P_ASZ;
        __nv_bfloat16* sBlo = stg[s] + 2 * P_ASZ + P_BSZ;
        #pragma unroll
        for (int i = 0; i < 2; i++) {
            int ai = tid * 2 + i, ar = ai >> 2, ac = (ai & 3) * 8;
            CP16(smem_u32(sAhi + ar * P_SA + ac), Ahi + (size_t)(bm + ar) * lda + k0 + ac);
            CP16(smem_u32(sAlo + ar * P_SA + ac), Alo + (size_t)(bm + ar) * lda + k0 + ac);
            int bi = tid * 2 + i, br = bi >> 3, bc = (bi & 7) * 8;
            CP16(smem_u32(sBhi + br * P_SB + bc), Bhi + (size_t)(k0 + br) * ldb + bn + bc);
            CP16(smem_u32(sBlo + br * P_SB + bc), Blo + (size_t)(k0 + br) * ldb + bn + bc);
        }
        asm volatile("cp.async.commit_group;\n");
    };

    const int niter = K / P_BK;
    issue_loads(0, 0);

    const int a_ro = (lane & 7) + ((lane >> 3) & 1) * 8;
    const int a_ko = ((lane >> 4) & 1) * 8;
    const int b_ro = (lane & 7) + ((lane >> 3) & 1) * 8;

    for (int it = 0; it < niter; it++) {
        int s = it & 1;
        if (it + 1 < niter) { issue_loads(s ^ 1, (it + 1) * P_BK);
                              asm volatile("cp.async.wait_group 1;\n"); }
        else                  asm volatile("cp.async.wait_group 0;\n");
        __syncthreads();

        const __nv_bfloat16* sAhi = stg[s];
        const __nv_bfloat16* sAlo = stg[s] + P_ASZ;
        const __nv_bfloat16* sBhi = stg[s] + 2 * P_ASZ;
        const __nv_bfloat16* sBlo = stg[s] + 2 * P_ASZ + P_BSZ;

        #pragma unroll
        for (int ks = 0; ks < P_BK; ks += 16) {
            uint32_t bh[4][2], bl[4][2];
            #pragma unroll
            for (int nf = 0; nf < 4; nf++) {
                ldsm_x2t(bh[nf], smem_u32(sBhi + (ks + b_ro) * P_SB + wn + nf * 8));
                ldsm_x2t(bl[nf], smem_u32(sBlo + (ks + b_ro) * P_SB + wn + nf * 8));
            }
            #pragma unroll
            for (int mf = 0; mf < 2; mf++) {
                uint32_t ah[4], al[4];
                int arow = wm + mf * 16 + a_ro;
                ldsm_x4(ah, smem_u32(sAhi + arow * P_SA + ks + a_ko));
                ldsm_x4(al, smem_u32(sAlo + arow * P_SA + ks + a_ko));
                #pragma unroll
                for (int nf = 0; nf < 4; nf++) {
                    mma16816(acc[mf][nf], ah, bh[nf]);
                    mma16816(acc[mf][nf], ah, bl[nf]);
                    mma16816(acc[mf][nf], al, bh[nf]);
                }
            }
        }
        __syncthreads();
    }

    #pragma unroll
    for (int mf = 0; mf < 2; mf++) {
        int row0 = bm + wm + mf * 16 + (lane >> 2);
        #pragma unroll
        for (int nf = 0; nf < 4; nf++) {
            int col = bn + wn + nf * 8 + (lane & 3) * 2;
            float b0 = bias[col], b1 = bias[col + 1];
            *(float2*)(C + (size_t)row0 * ldc + col) =
                make_float2(acc[mf][nf][0] + b0, acc[mf][nf][1] + b1);
            *(float2*)(C + (size_t)(row0 + 8) * ldc + col) =
                make_float2(acc[mf][nf][2] + b0, acc[mf][nf][3] + b1);
        }
    }
}

// ---------------- split fp32 -> (hi,lo) bf16 ---------------------------------
__global__ void split_k(const float* __restrict__ in, __nv_bfloat16* __restrict__ hi,
                        __nv_bfloat16* __restrict__ lo, int n)
{
    int i = blockIdx.x * blockDim.x + threadIdx.x;
    if (i < n) {
        float x = in[i];
        __nv_bfloat16 h = __float2bfloat16(x);
        hi[i] = h;
        lo[i] = __float2bfloat16(x - __bfloat162float(h));
    }
}

// ---------------- flash attend: streamed online softmax -----------------------
#define FA_CH 16
#define FA_NCH (LL/FA_CH)
#define FA_SMEM ((2*FA_CH*EE + EE + LL + FA_CH + FA_CH + 8) * 4)

__global__ __launch_bounds__(256) void attend_flash_k(
    const float* __restrict__ Mg, const int* __restrict__ mask,
    const int* __restrict__ lengths, float* __restrict__ out, int t)
{
    extern __shared__ float smf[];
    float* bufs[2] = { smf, smf + FA_CH * EE };
    float* smPQ   = smf + 2 * FA_CH * EE;
    float* smSall = smPQ + EE;
    float* smS16  = smSall + LL;
    float* smE    = smS16 + FA_CH;
    float* smMisc = smE + FA_CH;

    const int b = blockIdx.x, tid = threadIdx.x;
    const int warp = tid >> 5, lane = tid & 31;

    smPQ[tid] = g_PQ[b * EE + tid];
    const float* gM = Mg + (size_t)b * LL * EE;

    auto issue = [&](int c) {
        float* dst = bufs[c & 1];
        const float* src = gM + c * FA_CH * EE;
        #pragma unroll
        for (int i = 0; i < 4; i++) {
            int ch = tid + i * 256;
            CP16(smem_u32(dst + ch * 4), src + ch * 4);
        }
        asm volatile("cp.async.commit_group;\n");
    };

    issue(0);

    float a = 0.f;
    float m = -1e30f, d = 0.f;

    for (int c = 0; c < FA_NCH; c++) {
        if (c + 1 < FA_NCH) { issue(c + 1); asm volatile("cp.async.wait_group 1;\n"); }
        else                  asm volatile("cp.async.wait_group 0;\n");
        __syncthreads();
        float* smM = bufs[c & 1];

        #pragma unroll
        for (int rr = 0; rr < 2; rr++) {
            int l = rr * 8 + warp;
            float s = 0.f;
            #pragma unroll
            for (int j = 0; j < EE / 32; j++)
                s += smM[l * EE + lane + j * 32] * smPQ[lane + j * 32];
            #pragma unroll
            for (int o = 16; o; o >>= 1) s += __shfl_xor_sync(0xffffffffu, s, o);
            if (lane == 0) {
                int gl = c * FA_CH + l;
                float sv = (mask[b * LL + gl] != 0) ? -1e30f : s;
                smS16[l] = sv;
                smSall[gl] = sv;
            }
        }
        __syncthreads();

        if (warp == 0) {
            float sl = (lane < FA_CH) ? smS16[lane] : -1e30f;
            float mc = sl;
            #pragma unroll
            for (int o = 16; o; o >>= 1) mc = fmaxf(mc, __shfl_xor_sync(0xffffffffu, mc, o));
            float m_new = fmaxf(m, mc);
            float scale = expf(m - m_new);
            float e = (lane < FA_CH) ? expf(sl - m_new) : 0.f;
            float esum = e;
            #pragma unroll
            for (int o = 16; o; o >>= 1) esum += __shfl_xor_sync(0xffffffffu, esum, o);
            d = d * scale + esum;
            m = m_new;
            if (lane < FA_CH) smE[lane] = e;
            if (lane == 0) smMisc[0] = scale;
        }
        __syncthreads();

        float sc = smMisc[0];
        a *= sc;
        #pragma unroll
        for (int l = 0; l < FA_CH; l++)
            a += smE[l] * smM[l * EE + tid];
        __syncthreads();
    }

    if (warp == 0 && lane == 0) { smMisc[1] = m; smMisc[2] = 1.f / d; }
    __syncthreads();
    float m_fin = smMisc[1], inv_d = smMisc[2];

    float app = a * inv_d;
    __nv_bfloat16 h = __float2bfloat16(app);
    g_Xhi[(size_t)b * XW + tid] = h;
    g_Xlo[(size_t)b * XW + tid] = __float2bfloat16(app - __bfloat162float(h));

    if (tid < LL) {
        int len = lengths[b];
        len = min(max(len, 0), TT);
        if (len == t) out[(size_t)b * LL + tid] = expf(smSall[tid] - m_fin) * inv_d;
    }
}

// ---------------- LSTM cell --------------------------------------------------
__global__ void lstm_k(const int* __restrict__ msg, int t)
{
    int idx = blockIdx.x * blockDim.x + threadIdx.x;
    int b = idx >> 9, j = idx & (HH - 1);
    int tok = msg[b * TT + t];
    const float* ga = g_GATT + (size_t)b * G4;
    const float* pe = g_ProjEmb + (size_t)tok * G4;
    float gi = ga[j]          + pe[j]          + g_BiasC[j];
    float gf = ga[HH + j]     + pe[HH + j]     + g_BiasC[HH + j];
    float gg = ga[2 * HH + j] + pe[2 * HH + j] + g_BiasC[2 * HH + j];
    float go = ga[3 * HH + j] + pe[3 * HH + j] + g_BiasC[3 * HH + j];
    float c  = g_C[idx];
    float si = 1.f / (1.f + expf(-gi));
    float sf = 1.f / (1.f + expf(-gf));
    float so = 1.f / (1.f + expf(-go));
    float cn = sf * c + si * tanhf(gg);
    float hn = so * tanhf(cn);
    g_C[idx] = cn;
    __nv_bfloat16 hb = __float2bfloat16(hn);
    g_Xhi[(size_t)b * XW + EE + j] = hb;
    g_Xlo[(size_t)b * XW + EE + j] = __float2bfloat16(hn - __bfloat162float(hb));
}

// ---------------- bias_comb --------------------------------------------------
__global__ void biascomb_k(const float* __restrict__ b_ih, const float* __restrict__ b_hh,
                           const float* __restrict__ bc, const float* __restrict__ W_hh)
{
    int j = blockIdx.x, lane = threadIdx.x;
    float s = 0.f;
    for (int h = lane; h < HH; h += 32) s += bc[h] * W_hh[(size_t)j * HH + h];
    #pragma unroll
    for (int o = 16; o; o >>= 1) s += __shfl_xor_sync(0xffffffffu, s, o);
    if (lane == 0) g_BiasC[j] = b_ih[j] + b_hh[j] + s;
}

// ---------------- init -------------------------------------------------------
__global__ void init_k(const float* __restrict__ bq)
{
    int idx = blockIdx.x * blockDim.x + threadIdx.x;
    if (idx < BSZ * HH) {
        g_C[idx] = 0.f;
        int b = idx >> 9, j = idx & (HH - 1);
        g_Xhi[(size_t)b * XW + EE + j] = __float2bfloat16(0.f);
        g_Xlo[(size_t)b * XW + EE + j] = __float2bfloat16(0.f);
    }
    if (idx < BSZ * EE) g_PQ[idx] = bq[idx & (EE - 1)];
}

__global__ void zerotail_k(float* __restrict__ p, int n)
{
    int i = blockIdx.x * blockDim.x + threadIdx.x;
    if (i < n) p[i] = 0.f;
}

// ---------------- driver -----------------------------------------------------
extern "C" void kernel_launch(void* const* d_in, const int* in_sizes, int n_in,
                              void* d_out, int out_size)
{
    const int*   msg     = (const int*)d_in[0];
    const float* Mg      = (const float*)d_in[1];
    const int*   mask    = (const int*)d_in[2];
    const int*   lengths = (const int*)d_in[3];
    const float* emb     = (const float*)d_in[4];
    const float* Wq      = (const float*)d_in[5];
    const float* bq      = (const float*)d_in[6];
    const float* Wc      = (const float*)d_in[7];
    const float* bc      = (const float*)d_in[8];
    const float* W_ih    = (const float*)d_in[9];
    const float* W_hh    = (const float*)d_in[10];
    const float* b_ih    = (const float*)d_in[11];
    const float* b_hh    = (const float*)d_in[12];
    float* out = (float*)d_out;
    int Vp1 = in_sizes[4] / EE;
    if (Vp1 > VMAX) Vp1 = VMAX;

    float *pPQ, *pGATT, *pWqT, *pWihT, *pWcT, *pWhhT, *pWcomb, *pPE;
    __nv_bfloat16 *pXhi, *pXlo, *pWhi, *pWlo, *pWqThi, *pWqTlo;
    cudaGetSymbolAddress((void**)&pPQ,    g_PQ);
    cudaGetSymbolAddress((void**)&pGATT,  g_GATT);
    cudaGetSymbolAddress((void**)&pWqT,   g_WqT);
    cudaGetSymbolAddress((void**)&pWihT,  g_WihT);
    cudaGetSymbolAddress((void**)&pWcT,   g_WcT);
    cudaGetSymbolAddress((void**)&pWhhT,  g_WhhT);
    cudaGetSymbolAddress((void**)&pWcomb, g_Wcomb);
    cudaGetSymbolAddress((void**)&pPE,    g_ProjEmb);
    cudaGetSymbolAddress((void**)&pXhi,   g_Xhi);
    cudaGetSymbolAddress((void**)&pXlo,   g_Xlo);
    cudaGetSymbolAddress((void**)&pWhi,   g_Whi);
    cudaGetSymbolAddress((void**)&pWlo,   g_Wlo);
    cudaGetSymbolAddress((void**)&pWqThi, g_WqThi);
    cudaGetSymbolAddress((void**)&pWqTlo, g_WqTlo);

    cudaFuncSetAttribute(attend_flash_k, cudaFuncAttributeMaxDynamicSharedMemorySize, FA_SMEM);
    cudaFuncSetAttribute(mma_gates_k, cudaFuncAttributeMaxDynamicSharedMemorySize, GT_SMEM);
    cudaFuncSetAttribute(mma_pq_k,    cudaFuncAttributeMaxDynamicSharedMemorySize, P_SMEM);

    dim3 tb(32, 8);
    transpose_k<<<dim3(16, 8),  tb>>>(Wq,   pWqT,  EE, HH);
    transpose_k<<<dim3(8, 64),  tb>>>(W_ih, pWihT, G4, EE);
    transpose_k<<<dim3(24, 16), tb>>>(Wc,   pWcT,  HH, XW);
    transpose_k<<<dim3(16, 64), tb>>>(W_hh, pWhhT, G4, HH);

    gemm_k<<<dim3(G4 / 64, XW / 64), 256>>>(pWcT, pWhhT, pWcomb, nullptr,
                                            XW, G4, HH, HH, G4, G4);
    gemm_k<<<dim3(G4 / 64, (Vp1 + 63) / 64), 256>>>(emb, pWihT, pPE, nullptr,
                                                    Vp1, G4, EE, EE, G4, G4);
    split_k<<<(XW * G4 + 255) / 256, 256>>>(pWcomb, pWhi, pWlo, XW * G4);
    split_k<<<(HH * EE + 255) / 256, 256>>>(pWqT, pWqThi, pWqTlo, HH * EE);
    biascomb_k<<<G4, 32>>>(b_ih, b_hh, bc, W_hh);
    init_k<<<(BSZ * HH + 255) / 256, 256>>>(bq);

    if (out_size > BSZ * LL) {
        int ntail = out_size - BSZ * LL;
        zerotail_k<<<(ntail + 255) / 256, 256>>>(out + BSZ * LL, ntail);
    }

    for (int t = 0; t < TT; t++) {
        attend_flash_k<<<BSZ, 256, FA_SMEM>>>(Mg, mask, lengths, out, t);
        mma_gates_k<<<dim3(G4 / GT_BN, BSZ / GT_BM), 128, GT_SMEM>>>(
            pXhi, pXlo, pWhi, pWlo, pGATT, XW, G4, G4);
        lstm_k<<<(BSZ * HH) / 256, 256>>>(msg, t);
        mma_pq_k<<<dim3(EE / P_BN, BSZ / P_BM), 128, P_SMEM>>>(
            pXhi + EE, pXlo + EE, pWqThi, pWqTlo, pPQ, bq,
            BSZ, EE, HH, XW, EE, EE);
    }
    attend_flash_k<<<BSZ, 256, FA_SMEM>>>(Mg, mask, lengths, out, TT);
}

// round 7
// speedup vs baseline: 1.0478x; 1.0478x over previous
#include <cuda_runtime.h>
#include <cuda_bf16.h>
#include <math.h>
#include <stdint.h>

#define BSZ 1024
#define LL  128
#define EE  256
#define HH  512
#define TT  20
#define G4  (4*HH)    // 2048
#define XW  (EE+HH)   // 768
#define VMAX 1024

// ---------------- persistent scratch ----------------------------------------
__device__ float g_C[BSZ*HH];
__device__ float g_PQ[BSZ*EE];
__device__ float g_WqT[HH*EE];
__device__ float g_WihT[EE*G4];
__device__ float g_WcT[XW*HH];
__device__ float g_WhhT[HH*G4];
__device__ float g_Wcomb[XW*G4];
__device__ float g_ProjEmb[VMAX*G4];
__device__ float g_ProjEmbP[VMAX*G4];      // gate-interleaved cols: j*4+g
__device__ float g_BiasC[G4];
__device__ float g_BiasCP[G4];             // gate-interleaved
__device__ __nv_bfloat16 g_Xhi0[BSZ*XW];   // double-buffered [applied | h]
__device__ __nv_bfloat16 g_Xlo0[BSZ*XW];
__device__ __nv_bfloat16 g_Xhi1[BSZ*XW];
__device__ __nv_bfloat16 g_Xlo1[BSZ*XW];
__device__ __nv_bfloat16 g_Whi[XW*G4];     // Wcomb split, [K,N] gate-interleaved
__device__ __nv_bfloat16 g_Wlo[XW*G4];
__device__ __nv_bfloat16 g_WqThi[HH*EE];
__device__ __nv_bfloat16 g_WqTlo[HH*EE];

__device__ __forceinline__ uint32_t smem_u32(const void* p) {
    return (uint32_t)__cvta_generic_to_shared(p);
}
#define CP16(dst, src) asm volatile("cp.async.cg.shared.global [%0], [%1], 16;\n" :: "r"(dst), "l"(src))

// ---------------- transpose --------------------------------------------------
__global__ void transpose_k(const float* __restrict__ in, float* __restrict__ out,
                            int rows, int cols)
{
    __shared__ float tile[32][33];
    int x0 = blockIdx.x * 32, y0 = blockIdx.y * 32;
    int tx = threadIdx.x;
    for (int j = threadIdx.y; j < 32; j += 8) {
        int r = y0 + j, c = x0 + tx;
        if (r < rows && c < cols) tile[j][tx] = in[(size_t)r * cols + c];
    }
    __syncthreads();
    for (int j = threadIdx.y; j < 32; j += 8) {
        int orow = x0 + j, ocol = y0 + tx;
        if (orow < cols && ocol < rows) out[(size_t)orow * rows + ocol] = tile[tx][j];
    }
}

// ---------------- fp32 tiled GEMM (setup only) -------------------------------
__global__ __launch_bounds__(256) void gemm_k(
    const float* __restrict__ A, const float* __restrict__ B,
    float* __restrict__ C, const float* __restrict__ bias,
    int M, int N, int K, int lda, int ldb, int ldc)
{
    __shared__ float As[16][68];
    __shared__ float Bs[16][68];
    const int tid = threadIdx.x;
    const int tx  = tid & 15, ty = tid >> 4;
    const int bm  = blockIdx.y << 6, bn = blockIdx.x << 6;
    const int arow = tid >> 2, ak = (tid & 3) << 2;
    const int brow = tid >> 4, bcol = (tid & 15) << 2;

    float acc[4][4];
    #pragma unroll
    for (int i = 0; i < 4; i++)
        #pragma unroll
        for (int j = 0; j < 4; j++) acc[i][j] = 0.f;

    const bool aval = (bm + arow) < M;
    const float* Aptr = A + (size_t)(bm + arow) * lda + ak;
    const float* Bptr = B + (size_t)brow * ldb + bn + bcol;

    for (int k0 = 0; k0 < K; k0 += 16) {
        float4 av = aval ? *(const float4*)(Aptr + k0)
                         : make_float4(0.f, 0.f, 0.f, 0.f);
        As[ak + 0][arow] = av.x; As[ak + 1][arow] = av.y;
        As[ak + 2][arow] = av.z; As[ak + 3][arow] = av.w;
        float4 bv = *(const float4*)(Bptr + (size_t)k0 * ldb);
        *(float4*)(&Bs[brow][bcol]) = bv;
        __syncthreads();
        #pragma unroll
        for (int k = 0; k < 16; k++) {
            float4 a = *(const float4*)(&As[k][ty << 2]);
            float4 b = *(const float4*)(&Bs[k][tx << 2]);
            acc[0][0] += a.x * b.x; acc[0][1] += a.x * b.y; acc[0][2] += a.x * b.z; acc[0][3] += a.x * b.w;
            acc[1][0] += a.y * b.x; acc[1][1] += a.y * b.y; acc[1][2] += a.y * b.z; acc[1][3] += a.y * b.w;
            acc[2][0] += a.z * b.x; acc[2][1] += a.z * b.y; acc[2][2] += a.z * b.z; acc[2][3] += a.z * b.w;
            acc[3][0] += a.w * b.x; acc[3][1] += a.w * b.y; acc[3][2] += a.w * b.z; acc[3][3] += a.w * b.w;
        }
        __syncthreads();
    }

    float4 bb = bias ? *(const float4*)(bias + bn + (tx << 2))
                     : make_float4(0.f, 0.f, 0.f, 0.f);
    #pragma unroll
    for (int i = 0; i < 4; i++) {
        int row = bm + (ty << 2) + i;
        if (row < M) {
            float4 o;
            o.x = acc[i][0] + bb.x; o.y = acc[i][1] + bb.y;
            o.z = acc[i][2] + bb.z; o.w = acc[i][3] + bb.w;
            *(float4*)(C + (size_t)row * ldc + bn + (tx << 2)) = o;
        }
    }
}

// ---------------- MMA helpers --------------------------------------------------
__device__ __forceinline__ void ldsm_x4(uint32_t r[4], uint32_t addr) {
    asm volatile("ldmatrix.sync.aligned.m8n8.x4.shared.b16 {%0,%1,%2,%3}, [%4];\n"
        : "=r"(r[0]), "=r"(r[1]), "=r"(r[2]), "=r"(r[3]) : "r"(addr));
}
__device__ __forceinline__ void ldsm_x2t(uint32_t r[2], uint32_t addr) {
    asm volatile("ldmatrix.sync.aligned.m8n8.x2.trans.shared.b16 {%0,%1}, [%2];\n"
        : "=r"(r[0]), "=r"(r[1]) : "r"(addr));
}
__device__ __forceinline__ void mma16816(float* c, const uint32_t a[4], const uint32_t b[2]) {
    asm volatile(
        "mma.sync.aligned.m16n8k16.row.col.f32.bf16.bf16.f32 "
        "{%0,%1,%2,%3}, {%4,%5,%6,%7}, {%8,%9}, {%0,%1,%2,%3};\n"
        : "+f"(c[0]), "+f"(c[1]), "+f"(c[2]), "+f"(c[3])
        : "r"(a[0]), "r"(a[1]), "r"(a[2]), "r"(a[3]), "r"(b[0]), "r"(b[1]));
}

// ---------------- gates GEMM + fused LSTM (128x128x32, 256 thr) ---------------
// Gate-interleaved B cols (j*4+g). Epilogue: stage acc in smem, LSTM, write h.
#define MM_SA 40
#define MM_SB 136
#define MM_BM 128
#define MM_BN 128
#define MM_BK 32
#define MM_ASZ (MM_BM*MM_SA)
#define MM_BSZ (MM_BK*MM_SB)
#define MM_STG (2*MM_ASZ + 2*MM_BSZ)
#define MM_SMEM (2*MM_STG*2)    // 75776 B; also holds 128x132 f32 epilogue tile

__global__ __launch_bounds__(256, 1) void mma_gates_fused_k(
    const __nv_bfloat16* __restrict__ Ahi, const __nv_bfloat16* __restrict__ Alo,
    const __nv_bfloat16* __restrict__ Bhi, const __nv_bfloat16* __restrict__ Blo,
    const int* __restrict__ msg, int t,
    __nv_bfloat16* __restrict__ Xnhi, __nv_bfloat16* __restrict__ Xnlo)
{
    extern __shared__ __nv_bfloat16 sm[];
    __nv_bfloat16* stg[2] = { sm, sm + MM_STG };

    const int tid  = threadIdx.x;
    const int lane = tid & 31, warp = tid >> 5;
    const int bm = blockIdx.y * MM_BM, bn = blockIdx.x * MM_BN;
    const int wm = (warp >> 2) * 64, wn = (warp & 3) * 32;

    float acc[4][4][4];
    #pragma unroll
    for (int i = 0; i < 4; i++)
        #pragma unroll
        for (int j = 0; j < 4; j++)
            #pragma unroll
            for (int l = 0; l < 4; l++) acc[i][j][l] = 0.f;

    auto issue_loads = [&](int s, int k0) {
        __nv_bfloat16* sAhi = stg[s];
        __nv_bfloat16* sAlo = stg[s] + MM_ASZ;
        __nv_bfloat16* sBhi = stg[s] + 2 * MM_ASZ;
        __nv_bfloat16* sBlo = stg[s] + 2 * MM_ASZ + MM_BSZ;
        #pragma unroll
        for (int i = 0; i < 2; i++) {
            int ai = tid * 2 + i, ar = ai >> 2, ac = (ai & 3) * 8;
            CP16(smem_u32(sAhi + ar * MM_SA + ac), Ahi + (size_t)(bm + ar) * XW + k0 + ac);
            CP16(smem_u32(sAlo + ar * MM_SA + ac), Alo + (size_t)(bm + ar) * XW + k0 + ac);
            int bi = tid * 2 + i, br = bi >> 4, bc = (bi & 15) * 8;
            CP16(smem_u32(sBhi + br * MM_SB + bc), Bhi + (size_t)(k0 + br) * G4 + bn + bc);
            CP16(smem_u32(sBlo + br * MM_SB + bc), Blo + (size_t)(k0 + br) * G4 + bn + bc);
        }
        asm volatile("cp.async.commit_group;\n");
    };

    const int niter = XW / MM_BK;   // 24
    issue_loads(0, 0);

    const int a_ro = (lane & 7) + ((lane >> 3) & 1) * 8;
    const int a_ko = ((lane >> 4) & 1) * 8;
    const int b_ro = (lane & 7) + ((lane >> 3) & 1) * 8;

    for (int it = 0; it < niter; it++) {
        int s = it & 1;
        if (it + 1 < niter) { issue_loads(s ^ 1, (it + 1) * MM_BK);
                              asm volatile("cp.async.wait_group 1;\n"); }
        else                  asm volatile("cp.async.wait_group 0;\n");
        __syncthreads();

        const __nv_bfloat16* sAhi = stg[s];
        const __nv_bfloat16* sAlo = stg[s] + MM_ASZ;
        const __nv_bfloat16* sBhi = stg[s] + 2 * MM_ASZ;
        const __nv_bfloat16* sBlo = stg[s] + 2 * MM_ASZ + MM_BSZ;

        #pragma unroll
        for (int ks = 0; ks < MM_BK; ks += 16) {
            uint32_t bh[4][2], bl[4][2];
            #pragma unroll
            for (int nf = 0; nf < 4; nf++) {
                ldsm_x2t(bh[nf], smem_u32(sBhi + (ks + b_ro) * MM_SB + wn + nf * 8));
                ldsm_x2t(bl[nf], smem_u32(sBlo + (ks + b_ro) * MM_SB + wn + nf * 8));
            }
            #pragma unroll
            for (int mf = 0; mf < 4; mf++) {
                uint32_t ah[4], al[4];
                int arow = wm + mf * 16 + a_ro;
                ldsm_x4(ah, smem_u32(sAhi + arow * MM_SA + ks + a_ko));
                ldsm_x4(al, smem_u32(sAlo + arow * MM_SA + ks + a_ko));
                #pragma unroll
                for (int nf = 0; nf < 4; nf++) {
                    mma16816(acc[mf][nf], ah, bh[nf]);
                    mma16816(acc[mf][nf], ah, bl[nf]);
                    mma16816(acc[mf][nf], al, bh[nf]);
                }
            }
        }
        __syncthreads();
    }

    // ---- epilogue: stage acc in smem (128 x 132 f32), fused LSTM ----
    float* smF = (float*)sm;
    #pragma unroll
    for (int mf = 0; mf < 4; mf++) {
        int r0 = wm + mf * 16 + (lane >> 2);
        #pragma unroll
        for (int nf = 0; nf < 4; nf++) {
            int col = wn + nf * 8 + (lane & 3) * 2;
            *(float2*)(smF + r0 * 132 + col)       = make_float2(acc[mf][nf][0], acc[mf][nf][1]);
            *(float2*)(smF + (r0 + 8) * 132 + col) = make_float2(acc[mf][nf][2], acc[mf][nf][3]);
        }
    }
    __syncthreads();

    // 4096 (row, jj) pairs; j_global = bn/4 + jj; permuted cols = bn + jj*4 + g
    const int j0 = bn >> 2;
    #pragma unroll
    for (int i = 0; i < 16; i++) {
        int idx = tid + i * 256;
        int row = idx >> 5, jj = idx & 31;
        int b = bm + row, j = j0 + jj;
        int tok = msg[b * TT + t];
        float4 pe = *(const float4*)(g_ProjEmbP + (size_t)tok * G4 + bn + jj * 4);
        float4 bi = *(const float4*)(g_BiasCP + bn + jj * 4);
        const float* sr = smF + row * 132 + jj * 4;
        float gi = sr[0] + pe.x + bi.x;
        float gf = sr[1] + pe.y + bi.y;
        float gg = sr[2] + pe.z + bi.z;
        float go = sr[3] + pe.w + bi.w;
        float c  = g_C[b * HH + j];
        float si = 1.f / (1.f + expf(-gi));
        float sf = 1.f / (1.f + expf(-gf));
        float so = 1.f / (1.f + expf(-go));
        float cn = sf * c + si * tanhf(gg);
        float hn = so * tanhf(cn);
        g_C[b * HH + j] = cn;
        __nv_bfloat16 hb = __float2bfloat16(hn);
        Xnhi[(size_t)b * XW + EE + j] = hb;
        Xnlo[(size_t)b * XW + EE + j] = __float2bfloat16(hn - __bfloat162float(hb));
    }
}

// ---------------- split-bf16 pq GEMM (64x64x32, 128 thr) ----------------------
#define P_SA 40
#define P_SB 72
#define P_BM 64
#define P_BN 64
#define P_BK 32
#define P_ASZ (P_BM*P_SA)
#define P_BSZ (P_BK*P_SB)
#define P_STG (2*P_ASZ + 2*P_BSZ)
#define P_SMEM (2*P_STG*2)

__global__ __launch_bounds__(128) void mma_pq_k(
    const __nv_bfloat16* __restrict__ Ahi, const __nv_bfloat16* __restrict__ Alo,
    const __nv_bfloat16* __restrict__ Bhi, const __nv_bfloat16* __restrict__ Blo,
    float* __restrict__ C, const float* __restrict__ bias,
    int M, int N, int K, int lda, int ldb, int ldc)
{
    extern __shared__ __nv_bfloat16 smb[];
    __nv_bfloat16* stg[2] = { smb, smb + P_STG };

    const int tid  = threadIdx.x;
    const int lane = tid & 31, warp = tid >> 5;
    const int bm = blockIdx.y * P_BM, bn = blockIdx.x * P_BN;
    const int wm = (warp >> 1) * 32, wn = (warp & 1) * 32;

    float acc[2][4][4];
    #pragma unroll
    for (int i = 0; i < 2; i++)
        #pragma unroll
        for (int j = 0; j < 4; j++)
            #pragma unroll
            for (int l = 0; l < 4; l++) acc[i][j][l] = 0.f;

    auto issue_loads = [&](int s, int k0) {
        __nv_bfloat16* sAhi = stg[s];
        __nv_bfloat16* sAlo = stg[s] + P_ASZ;
        __nv_bfloat16* sBhi = stg[s] + 2 * P_ASZ;
        __nv_bfloat16* sBlo = stg[s] + 2 * P_ASZ + P_BSZ;
        #pragma unroll
        for (int i = 0; i < 2; i++) {
            int ai = tid * 2 + i, ar = ai >> 2, ac = (ai & 3) * 8;
            CP16(smem_u32(sAhi + ar * P_SA + ac), Ahi + (size_t)(bm + ar) * lda + k0 + ac);
            CP16(smem_u32(sAlo + ar * P_SA + ac), Alo + (size_t)(bm + ar) * lda + k0 + ac);
            int bi = tid * 2 + i, br = bi >> 3, bc = (bi & 7) * 8;
            CP16(smem_u32(sBhi + br * P_SB + bc), Bhi + (size_t)(k0 + br) * ldb + bn + bc);
            CP16(smem_u32(sBlo + br * P_SB + bc), Blo + (size_t)(k0 + br) * ldb + bn + bc);
        }
        asm volatile("cp.async.commit_group;\n");
    };

    const int niter = K / P_BK;
    issue_loads(0, 0);

    const int a_ro = (lane & 7) + ((lane >> 3) & 1) * 8;
    const int a_ko = ((lane >> 4) & 1) * 8;
    const int b_ro = (lane & 7) + ((lane >> 3) & 1) * 8;

    for (int it = 0; it < niter; it++) {
        int s = it & 1;
        if (it + 1 < niter) { issue_loads(s ^ 1, (it + 1) * P_BK);
                              asm volatile("cp.async.wait_group 1;\n"); }
        else                  asm volatile("cp.async.wait_group 0;\n");
        __syncthreads();

        const __nv_bfloat16* sAhi = stg[s];
        const __nv_bfloat16* sAlo = stg[s] + P_ASZ;
        const __nv_bfloat16* sBhi = stg[s] + 2 * P_ASZ;
        const __nv_bfloat16* sBlo = stg[s] + 2 * P_ASZ + P_BSZ;

        #pragma unroll
        for (int ks = 0; ks < P_BK; ks += 16) {
            uint32_t bh[4][2], bl[4][2];
            #pragma unroll
            for (int nf = 0; nf < 4; nf++) {
                ldsm_x2t(bh[nf], smem_u32(sBhi + (ks + b_ro) * P_SB + wn + nf * 8));
                ldsm_x2t(bl[nf], smem_u32(sBlo + (ks + b_ro) * P_SB + wn + nf * 8));
            }
            #pragma unroll
            for (int mf = 0; mf < 2; mf++) {
                uint32_t ah[4], al[4];
                int arow = wm + mf * 16 + a_ro;
                ldsm_x4(ah, smem_u32(sAhi + arow * P_SA + ks + a_ko));
                ldsm_x4(al, smem_u32(sAlo + arow * P_SA + ks + a_ko));
                #pragma unroll
                for (int nf = 0; nf < 4; nf++) {
                    mma16816(acc[mf][nf], ah, bh[nf]);
                    mma16816(acc[mf][nf], ah, bl[nf]);
                    mma16816(acc[mf][nf], al, bh[nf]);
                }
            }
        }
        __syncthreads();
    }

    #pragma unroll
    for (int mf = 0; mf < 2; mf++) {
        int row0 = bm + wm + mf * 16 + (lane >> 2);
        #pragma unroll
        for (int nf = 0; nf < 4; nf++) {
            int col = bn + wn + nf * 8 + (lane & 3) * 2;
            float b0 = bias[col], b1 = bias[col + 1];
            *(float2*)(C + (size_t)row0 * ldc + col) =
                make_float2(acc[mf][nf][0] + b0, acc[mf][nf][1] + b1);
            *(float2*)(C + (size_t)(row0 + 8) * ldc + col) =
                make_float2(acc[mf][nf][2] + b0, acc[mf][nf][3] + b1);
        }
    }
}

// ---------------- split fp32 -> (hi,lo) bf16 ---------------------------------
__global__ void split_k(const float* __restrict__ in, __nv_bfloat16* __restrict__ hi,
                        __nv_bfloat16* __restrict__ lo, int n)
{
    int i = blockIdx.x * blockDim.x + threadIdx.x;
    if (i < n) {
        float x = in[i];
        __nv_bfloat16 h = __float2bfloat16(x);
        hi[i] = h;
        lo[i] = __float2bfloat16(x - __bfloat162float(h));
    }
}

// split Wcomb with gate-interleave permutation: newcol = j*4+g (old g*512+j)
__global__ void split_perm_k(const float* __restrict__ in,
                             __nv_bfloat16* __restrict__ hi,
                             __nv_bfloat16* __restrict__ lo, int n)
{
    int i = blockIdx.x * blockDim.x + threadIdx.x;
    if (i < n) {
        int k = i / G4, cin = i - k * G4;
        int g = cin >> 9, j = cin & 511;
        int cout = j * 4 + g;
        float x = in[i];
        __nv_bfloat16 h = __float2bfloat16(x);
        hi[(size_t)k * G4 + cout] = h;
        lo[(size_t)k * G4 + cout] = __float2bfloat16(x - __bfloat162float(h));
    }
}

// permute ProjEmb cols (and BiasC via rows==1 trick done separately)
__global__ void perm_pe_k(const float* __restrict__ in, float* __restrict__ out,
                          int rows)
{
    int i = blockIdx.x * blockDim.x + threadIdx.x;
    if (i < rows * G4) {
        int r = i / G4, cin = i - r * G4;
        int g = cin >> 9, j = cin & 511;
        out[(size_t)r * G4 + j * 4 + g] = in[i];
    }
}

// ---------------- flash attend: streamed online softmax -----------------------
#define FA_CH 16
#define FA_NCH (LL/FA_CH)
#define FA_SMEM ((2*FA_CH*EE + EE + LL + FA_CH + FA_CH + 8) * 4)

__global__ __launch_bounds__(256) void attend_flash_k(
    const float* __restrict__ Mg, const int* __restrict__ mask,
    const int* __restrict__ lengths, float* __restrict__ out, int t,
    __nv_bfloat16* __restrict__ Xhi, __nv_bfloat16* __restrict__ Xlo)
{
    extern __shared__ float smf[];
    float* bufs[2] = { smf, smf + FA_CH * EE };
    float* smPQ   = smf + 2 * FA_CH * EE;
    float* smSall = smPQ + EE;
    float* smS16  = smSall + LL;
    float* smE    = smS16 + FA_CH;
    float* smMisc = smE + FA_CH;

    const int b = blockIdx.x, tid = threadIdx.x;
    const int warp = tid >> 5, lane = tid & 31;

    smPQ[tid] = g_PQ[b * EE + tid];
    const float* gM = Mg + (size_t)b * LL * EE;

    auto issue = [&](int c) {
        float* dst = bufs[c & 1];
        const float* src = gM + c * FA_CH * EE;
        #pragma unroll
        for (int i = 0; i < 4; i++) {
            int ch = tid + i * 256;
            CP16(smem_u32(dst + ch * 4), src + ch * 4);
        }
        asm volatile("cp.async.commit_group;\n");
    };

    issue(0);

    float a = 0.f;
    float m = -1e30f, d = 0.f;

    for (int c = 0; c < FA_NCH; c++) {
        if (c + 1 < FA_NCH) { issue(c + 1); asm volatile("cp.async.wait_group 1;\n"); }
        else                  asm volatile("cp.async.wait_group 0;\n");
        __syncthreads();
        float* smM = bufs[c & 1];

        #pragma unroll
        for (int rr = 0; rr < 2; rr++) {
            int l = rr * 8 + warp;
            float s = 0.f;
            #pragma unroll
            for (int j = 0; j < EE / 32; j++)
                s += smM[l * EE + lane + j * 32] * smPQ[lane + j * 32];
            #pragma unroll
            for (int o = 16; o; o >>= 1) s += __shfl_xor_sync(0xffffffffu, s, o);
            if (lane == 0) {
                int gl = c * FA_CH + l;
                float sv = (mask[b * LL + gl] != 0) ? -1e30f : s;
                smS16[l] = sv;
                smSall[gl] = sv;
            }
        }
        __syncthreads();

        if (warp == 0) {
            float sl = (lane < FA_CH) ? smS16[lane] : -1e30f;
            float mc = sl;
            #pragma unroll
            for (int o = 16; o; o >>= 1) mc = fmaxf(mc, __shfl_xor_sync(0xffffffffu, mc, o));
            float m_new = fmaxf(m, mc);
            float scale = expf(m - m_new);
            float e = (lane < FA_CH) ? expf(sl - m_new) : 0.f;
            float esum = e;
            #pragma unroll
            for (int o = 16; o; o >>= 1) esum += __shfl_xor_sync(0xffffffffu, esum, o);
            d = d * scale + esum;
            m = m_new;
            if (lane < FA_CH) smE[lane] = e;
            if (lane == 0) smMisc[0] = scale;
        }
        __syncthreads();

        float sc = smMisc[0];
        a *= sc;
        #pragma unroll
        for (int l = 0; l < FA_CH; l++)
            a += smE[l] * smM[l * EE + tid];
        __syncthreads();
    }

    if (warp == 0 && lane == 0) { smMisc[1] = m; smMisc[2] = 1.f / d; }
    __syncthreads();
    float m_fin = smMisc[1], inv_d = smMisc[2];

    float app = a * inv_d;
    __nv_bfloat16 h = __float2bfloat16(app);
    Xhi[(size_t)b * XW + tid] = h;
    Xlo[(size_t)b * XW + tid] = __float2bfloat16(app - __bfloat162float(h));

    if (tid < LL) {
        int len = lengths[b];
        len = min(max(len, 0), TT);
        if (len == t) out[(size_t)b * LL + tid] = expf(smSall[tid] - m_fin) * inv_d;
    }
}

// ---------------- bias_comb --------------------------------------------------
__global__ void biascomb_k(const float* __restrict__ b_ih, const float* __restrict__ b_hh,
                           const float* __restrict__ bc, const float* __restrict__ W_hh)
{
    int j = blockIdx.x, lane = threadIdx.x;
    float s = 0.f;
    for (int h = lane; h < HH; h += 32) s += bc[h] * W_hh[(size_t)j * HH + h];
    #pragma unroll
    for (int o = 16; o; o >>= 1) s += __shfl_xor_sync(0xffffffffu, s, o);
    if (lane == 0) {
        float v = b_ih[j] + b_hh[j] + s;
        g_BiasC[j] = v;
        int g = j >> 9, jj = j & 511;
        g_BiasCP[jj * 4 + g] = v;
    }
}

// ---------------- init -------------------------------------------------------
__global__ void init_k(const float* __restrict__ bq)
{
    int idx = blockIdx.x * blockDim.x + threadIdx.x;
    if (idx < BSZ * HH) {
        g_C[idx] = 0.f;
        int b = idx >> 9, j = idx & (HH - 1);
        g_Xhi0[(size_t)b * XW + EE + j] = __float2bfloat16(0.f);
        g_Xlo0[(size_t)b * XW + EE + j] = __float2bfloat16(0.f);
    }
    if (idx < BSZ * EE) g_PQ[idx] = bq[idx & (EE - 1)];
}

__global__ void zerotail_k(float* __restrict__ p, int n)
{
    int i = blockIdx.x * blockDim.x + threadIdx.x;
    if (i < n) p[i] = 0.f;
}

// ---------------- driver -----------------------------------------------------
extern "C" void kernel_launch(void* const* d_in, const int* in_sizes, int n_in,
                              void* d_out, int out_size)
{
    const int*   msg     = (const int*)d_in[0];
    const float* Mg      = (const float*)d_in[1];
    const int*   mask    = (const int*)d_in[2];
    const int*   lengths = (const int*)d_in[3];
    const float* emb     = (const float*)d_in[4];
    const float* Wq      = (const float*)d_in[5];
    const float* bq      = (const float*)d_in[6];
    const float* Wc      = (const float*)d_in[7];
    const float* bc      = (const float*)d_in[8];
    const float* W_ih    = (const float*)d_in[9];
    const float* W_hh    = (const float*)d_in[10];
    const float* b_ih    = (const float*)d_in[11];
    const float* b_hh    = (const float*)d_in[12];
    float* out = (float*)d_out;
    int Vp1 = in_sizes[4] / EE;
    if (Vp1 > VMAX) Vp1 = VMAX;

    float *pPQ, *pWqT, *pWihT, *pWcT, *pWhhT, *pWcomb, *pPE, *pPEP;
    __nv_bfloat16 *pWhi, *pWlo, *pWqThi, *pWqTlo;
    __nv_bfloat16 *pXhi[2], *pXlo[2];
    cudaGetSymbolAddress((void**)&pPQ,    g_PQ);
    cudaGetSymbolAddress((void**)&pWqT,   g_WqT);
    cudaGetSymbolAddress((void**)&pWihT,  g_WihT);
    cudaGetSymbolAddress((void**)&pWcT,   g_WcT);
    cudaGetSymbolAddress((void**)&pWhhT,  g_WhhT);
    cudaGetSymbolAddress((void**)&pWcomb, g_Wcomb);
    cudaGetSymbolAddress((void**)&pPE,    g_ProjEmb);
    cudaGetSymbolAddress((void**)&pPEP,   g_ProjEmbP);
    cudaGetSymbolAddress((void**)&pWhi,   g_Whi);
    cudaGetSymbolAddress((void**)&pWlo,   g_Wlo);
    cudaGetSymbolAddress((void**)&pWqThi, g_WqThi);
    cudaGetSymbolAddress((void**)&pWqTlo, g_WqTlo);
    cudaGetSymbolAddress((void**)&pXhi[0], g_Xhi0);
    cudaGetSymbolAddress((void**)&pXlo[0], g_Xlo0);
    cudaGetSymbolAddress((void**)&pXhi[1], g_Xhi1);
    cudaGetSymbolAddress((void**)&pXlo[1], g_Xlo1);

    cudaFuncSetAttribute(attend_flash_k, cudaFuncAttributeMaxDynamicSharedMemorySize, FA_SMEM);
    cudaFuncSetAttribute(mma_gates_fused_k, cudaFuncAttributeMaxDynamicSharedMemorySize, MM_SMEM);
    cudaFuncSetAttribute(mma_pq_k, cudaFuncAttributeMaxDynamicSharedMemorySize, P_SMEM);

    dim3 tb(32, 8);
    transpose_k<<<dim3(16, 8),  tb>>>(Wq,   pWqT,  EE, HH);
    transpose_k<<<dim3(8, 64),  tb>>>(W_ih, pWihT, G4, EE);
    transpose_k<<<dim3(24, 16), tb>>>(Wc,   pWcT,  HH, XW);
    transpose_k<<<dim3(16, 64), tb>>>(W_hh, pWhhT, G4, HH);

    gemm_k<<<dim3(G4 / 64, XW / 64), 256>>>(pWcT, pWhhT, pWcomb, nullptr,
                                            XW, G4, HH, HH, G4, G4);
    gemm_k<<<dim3(G4 / 64, (Vp1 + 63) / 64), 256>>>(emb, pWihT, pPE, nullptr,
                                                    Vp1, G4, EE, EE, G4, G4);
    split_perm_k<<<(XW * G4 + 255) / 256, 256>>>(pWcomb, pWhi, pWlo, XW * G4);
    perm_pe_k<<<(Vp1 * G4 + 255) / 256, 256>>>(pPE, pPEP, Vp1);
    split_k<<<(HH * EE + 255) / 256, 256>>>(pWqT, pWqThi, pWqTlo, HH * EE);
    biascomb_k<<<G4, 32>>>(b_ih, b_hh, bc, W_hh);
    init_k<<<(BSZ * HH + 255) / 256, 256>>>(bq);

    if (out_size > BSZ * LL) {
        int ntail = out_size - BSZ * LL;
        zerotail_k<<<(ntail + 255) / 256, 256>>>(out + BSZ * LL, ntail);
    }

    for (int t = 0; t < TT; t++) {
        int cur = t & 1, nxt = cur ^ 1;
        attend_flash_k<<<BSZ, 256, FA_SMEM>>>(Mg, mask, lengths, out, t,
                                              pXhi[cur], pXlo[cur]);
        mma_gates_fused_k<<<dim3(G4 / MM_BN, BSZ / MM_BM), 256, MM_SMEM>>>(
            pXhi[cur], pXlo[cur], pWhi, pWlo, msg, t, pXhi[nxt], pXlo[nxt]);
        mma_pq_k<<<dim3(EE / P_BN, BSZ / P_BM), 128, P_SMEM>>>(
            pXhi[nxt] + EE, pXlo[nxt] + EE, pWqThi, pWqTlo, pPQ, bq,
            BSZ, EE, HH, XW, EE, EE);
    }
    attend_flash_k<<<BSZ, 256, FA_SMEM>>>(Mg, mask, lengths, out, TT,
                                          pXhi[0], pXlo[0]);
}

// round 8
// speedup vs baseline: 1.1500x; 1.0976x over previous
#include <cuda_runtime.h>
#include <cuda_bf16.h>
#include <math.h>
#include <stdint.h>

#define BSZ 1024
#define LL  128
#define EE  256
#define HH  512
#define TT  20
#define G4  (4*HH)    // 2048
#define XW  (EE+HH)   // 768
#define VMAX 1024

// ---------------- persistent scratch ----------------------------------------
__device__ float g_C[BSZ*HH];
__device__ float g_PQ[BSZ*EE];
__device__ float g_GATT[BSZ*G4];
__device__ float g_WqT[HH*EE];
__device__ float g_WihT[EE*G4];
__device__ float g_WcT[XW*HH];
__device__ float g_WhhT[HH*G4];
__device__ float g_ProjEmb[VMAX*G4];
__device__ float g_BiasC[G4];
__device__ __nv_bfloat16 g_Xhi[BSZ*XW];    // [applied | h] split-bf16
__device__ __nv_bfloat16 g_Xlo[BSZ*XW];
__device__ __nv_bfloat16 g_Whi[XW*G4];     // Wcomb split, [K,N]
__device__ __nv_bfloat16 g_Wlo[XW*G4];
__device__ __nv_bfloat16 g_WqThi[HH*EE];
__device__ __nv_bfloat16 g_WqTlo[HH*EE];

__device__ __forceinline__ uint32_t smem_u32(const void* p) {
    return (uint32_t)__cvta_generic_to_shared(p);
}
#define CP16(dst, src) asm volatile("cp.async.cg.shared.global [%0], [%1], 16;\n" :: "r"(dst), "l"(src))

// ---------------- prep: 4 transposes + biascomb + init + zerotail (1 launch) --
__device__ __forceinline__ void transpose_dev(const float* __restrict__ in,
                                              float* __restrict__ out,
                                              int rows, int cols)
{
    __shared__ float tile[32][33];
    int x0 = blockIdx.x * 32, y0 = blockIdx.y * 32;
    if (x0 >= cols || y0 >= rows) return;
    int tx = threadIdx.x;
    for (int j = threadIdx.y; j < 32; j += 8) {
        int r = y0 + j, c = x0 + tx;
        if (r < rows && c < cols) tile[j][tx] = in[(size_t)r * cols + c];
    }
    __syncthreads();
    for (int j = threadIdx.y; j < 32; j += 8) {
        int orow = x0 + j, ocol = y0 + tx;
        if (orow < cols && ocol < rows) out[(size_t)orow * rows + ocol] = tile[tx][j];
    }
}

__global__ void prep_k(const float* __restrict__ Wq, const float* __restrict__ W_ih,
                       const float* __restrict__ Wc, const float* __restrict__ W_hh,
                       const float* __restrict__ b_ih, const float* __restrict__ b_hh,
                       const float* __restrict__ bc, const float* __restrict__ bq,
                       float* __restrict__ out, int ntail)
{
    int z = blockIdx.z;
    if (z == 0)      { transpose_dev(Wq,   g_WqT,  EE, HH); return; }
    else if (z == 1) { transpose_dev(W_ih, g_WihT, G4, EE); return; }
    else if (z == 2) { transpose_dev(Wc,   g_WcT,  HH, XW); return; }
    else if (z == 3) { transpose_dev(W_hh, g_WhhT, G4, HH); return; }

    // z == 4: misc (grid-stride)
    const int tid  = threadIdx.y * 32 + threadIdx.x;
    const int lane = tid & 31, warp = tid >> 5;
    const int nb   = gridDim.x * gridDim.y;
    const int bid  = blockIdx.y * gridDim.x + blockIdx.x;

    // biascomb: one warp per j
    for (int j = bid * 8 + warp; j < G4; j += nb * 8) {
        float s = 0.f;
        for (int h = lane; h < HH; h += 32) s += bc[h] * W_hh[(size_t)j * HH + h];
        #pragma unroll
        for (int o = 16; o; o >>= 1) s += __shfl_xor_sync(0xffffffffu, s, o);
        if (lane == 0) g_BiasC[j] = b_ih[j] + b_hh[j] + s;
    }
    // init C=0, X h-part=0
    for (int i = bid * 256 + tid; i < BSZ * HH; i += nb * 256) {
        g_C[i] = 0.f;
        int b = i >> 9, j = i & (HH - 1);
        g_Xhi[(size_t)b * XW + EE + j] = __float2bfloat16(0.f);
        g_Xlo[(size_t)b * XW + EE + j] = __float2bfloat16(0.f);
    }
    // PQ = bq
    for (int i = bid * 256 + tid; i < BSZ * EE; i += nb * 256)
        g_PQ[i] = bq[i & (EE - 1)];
    // zero tail of output (logits/entropy)
    for (int i = bid * 256 + tid; i < ntail; i += nb * 256)
        out[BSZ * LL + i] = 0.f;
}

// ---------------- setup GEMMs (1 launch, z-sliced) ----------------------------
// mode 0: fp32 C. mode 1: split bf16 hi/lo.
__device__ __forceinline__ void gemm_dev(
    const float* __restrict__ A, const float* __restrict__ B,
    float* __restrict__ C, __nv_bfloat16* __restrict__ Chi,
    __nv_bfloat16* __restrict__ Clo,
    int M, int N, int K, int lda, int ldb, int ldc, int mode)
{
    __shared__ float As[16][68];
    __shared__ float Bs[16][68];
    const int tid = threadIdx.x;
    const int tx  = tid & 15, ty = tid >> 4;
    const int bm  = blockIdx.y << 6, bn = blockIdx.x << 6;
    if (bm >= M + 63 || bn >= N) {}
    const int arow = tid >> 2, ak = (tid & 3) << 2;
    const int brow = tid >> 4, bcol = (tid & 15) << 2;

    float acc[4][4];
    #pragma unroll
    for (int i = 0; i < 4; i++)
        #pragma unroll
        for (int j = 0; j < 4; j++) acc[i][j] = 0.f;

    const bool aval = (bm + arow) < M;
    const float* Aptr = A + (size_t)(bm + arow) * lda + ak;
    const float* Bptr = B + (size_t)brow * ldb + bn + bcol;

    for (int k0 = 0; k0 < K; k0 += 16) {
        float4 av = aval ? *(const float4*)(Aptr + k0)
                         : make_float4(0.f, 0.f, 0.f, 0.f);
        As[ak + 0][arow] = av.x; As[ak + 1][arow] = av.y;
        As[ak + 2][arow] = av.z; As[ak + 3][arow] = av.w;
        float4 bv = *(const float4*)(Bptr + (size_t)k0 * ldb);
        *(float4*)(&Bs[brow][bcol]) = bv;
        __syncthreads();
        #pragma unroll
        for (int k = 0; k < 16; k++) {
            float4 a = *(const float4*)(&As[k][ty << 2]);
            float4 b = *(const float4*)(&Bs[k][tx << 2]);
            acc[0][0] += a.x * b.x; acc[0][1] += a.x * b.y; acc[0][2] += a.x * b.z; acc[0][3] += a.x * b.w;
            acc[1][0] += a.y * b.x; acc[1][1] += a.y * b.y; acc[1][2] += a.y * b.z; acc[1][3] += a.y * b.w;
            acc[2][0] += a.z * b.x; acc[2][1] += a.z * b.y; acc[2][2] += a.z * b.z; acc[2][3] += a.z * b.w;
            acc[3][0] += a.w * b.x; acc[3][1] += a.w * b.y; acc[3][2] += a.w * b.z; acc[3][3] += a.w * b.w;
        }
        __syncthreads();
    }

    #pragma unroll
    for (int i = 0; i < 4; i++) {
        int row = bm + (ty << 2) + i;
        if (row < M) {
            if (mode == 0) {
                *(float4*)(C + (size_t)row * ldc + bn + (tx << 2)) =
                    make_float4(acc[i][0], acc[i][1], acc[i][2], acc[i][3]);
            } else {
                #pragma unroll
                for (int q = 0; q < 4; q++) {
                    float o = acc[i][q];
                    __nv_bfloat16 h = __float2bfloat16(o);
                    size_t off = (size_t)row * ldc + bn + (tx << 2) + q;
                    Chi[off] = h;
                    Clo[off] = __float2bfloat16(o - __bfloat162float(h));
                }
            }
        }
    }
}

__global__ __launch_bounds__(256) void gemm2_k(const float* __restrict__ emb, int Vp1)
{
    int z = blockIdx.z;
    if (z == 0) {
        if (blockIdx.y < 12)
            gemm_dev(g_WcT, g_WhhT, nullptr, g_Whi, g_Wlo,
                     XW, G4, HH, HH, G4, G4, 1);
    } else if (z == 1) {
        gemm_dev(emb, g_WihT, g_ProjEmb, nullptr, nullptr,
                 Vp1, G4, EE, EE, G4, G4, 0);
    } else {
        // split WqT: 512 blocks x 256 threads == HH*EE
        int bid = blockIdx.y * gridDim.x + blockIdx.x;
        int i = bid * 256 + threadIdx.x;
        if (i < HH * EE) {
            float x = g_WqT[i];
            __nv_bfloat16 h = __float2bfloat16(x);
            g_WqThi[i] = h;
            g_WqTlo[i] = __float2bfloat16(x - __bfloat162float(h));
        }
    }
}

// ---------------- MMA helpers --------------------------------------------------
__device__ __forceinline__ void ldsm_x4(uint32_t r[4], uint32_t addr) {
    asm volatile("ldmatrix.sync.aligned.m8n8.x4.shared.b16 {%0,%1,%2,%3}, [%4];\n"
        : "=r"(r[0]), "=r"(r[1]), "=r"(r[2]), "=r"(r[3]) : "r"(addr));
}
__device__ __forceinline__ void ldsm_x2t(uint32_t r[2], uint32_t addr) {
    asm volatile("ldmatrix.sync.aligned.m8n8.x2.trans.shared.b16 {%0,%1}, [%2];\n"
        : "=r"(r[0]), "=r"(r[1]) : "r"(addr));
}
__device__ __forceinline__ void mma16816(float* c, const uint32_t a[4], const uint32_t b[2]) {
    asm volatile(
        "mma.sync.aligned.m16n8k16.row.col.f32.bf16.bf16.f32 "
        "{%0,%1,%2,%3}, {%4,%5,%6,%7}, {%8,%9}, {%0,%1,%2,%3};\n"
        : "+f"(c[0]), "+f"(c[1]), "+f"(c[2]), "+f"(c[3])
        : "r"(a[0]), "r"(a[1]), "r"(a[2]), "r"(a[3]), "r"(b[0]), "r"(b[1]));
}

// ---------------- gates GEMM (128x128x32, 8 warps, 3-stage) -------------------
#define MM_SA 40
#define MM_SB 136
#define MM_BM 128
#define MM_BN 128
#define MM_BK 32
#define MM_ASZ (MM_BM*MM_SA)
#define MM_BSZ (MM_BK*MM_SB)
#define MM_STG (2*MM_ASZ + 2*MM_BSZ)   // 18944 elems
#define MM_NST 3
#define MM_SMEM (MM_NST*MM_STG*2)      // 113664 B

__global__ __launch_bounds__(256, 1) void mma_gemm_k(
    const __nv_bfloat16* __restrict__ Ahi, const __nv_bfloat16* __restrict__ Alo,
    const __nv_bfloat16* __restrict__ Bhi, const __nv_bfloat16* __restrict__ Blo,
    float* __restrict__ C)
{
    extern __shared__ __nv_bfloat16 sm[];
    __nv_bfloat16* stg[MM_NST] = { sm, sm + MM_STG, sm + 2 * MM_STG };

    const int tid  = threadIdx.x;
    const int lane = tid & 31, warp = tid >> 5;
    const int bm = blockIdx.y * MM_BM, bn = blockIdx.x * MM_BN;
    const int wm = (warp >> 2) * 64, wn = (warp & 3) * 32;

    float acc[4][4][4];
    #pragma unroll
    for (int i = 0; i < 4; i++)
        #pragma unroll
        for (int j = 0; j < 4; j++)
            #pragma unroll
            for (int l = 0; l < 4; l++) acc[i][j][l] = 0.f;

    auto issue_loads = [&](int s, int k0) {
        __nv_bfloat16* sAhi = stg[s];
        __nv_bfloat16* sAlo = stg[s] + MM_ASZ;
        __nv_bfloat16* sBhi = stg[s] + 2 * MM_ASZ;
        __nv_bfloat16* sBlo = stg[s] + 2 * MM_ASZ + MM_BSZ;
        #pragma unroll
        for (int i = 0; i < 2; i++) {
            int ai = tid * 2 + i, ar = ai >> 2, ac = (ai & 3) * 8;
            CP16(smem_u32(sAhi + ar * MM_SA + ac), Ahi + (size_t)(bm + ar) * XW + k0 + ac);
            CP16(smem_u32(sAlo + ar * MM_SA + ac), Alo + (size_t)(bm + ar) * XW + k0 + ac);
            int bi = tid * 2 + i, br = bi >> 4, bc = (bi & 15) * 8;
            CP16(smem_u32(sBhi + br * MM_SB + bc), Bhi + (size_t)(k0 + br) * G4 + bn + bc);
            CP16(smem_u32(sBlo + br * MM_SB + bc), Blo + (size_t)(k0 + br) * G4 + bn + bc);
        }
        asm volatile("cp.async.commit_group;\n");
    };

    const int niter = XW / MM_BK;   // 24
    issue_loads(0, 0);
    issue_loads(1, MM_BK);

    const int a_ro = (lane & 7) + ((lane >> 3) & 1) * 8;
    const int a_ko = ((lane >> 4) & 1) * 8;
    const int b_ro = (lane & 7) + ((lane >> 3) & 1) * 8;

    for (int it = 0; it < niter; it++) {
        if (it + 2 < niter) { issue_loads((it + 2) % MM_NST, (it + 2) * MM_BK);
                              asm volatile("cp.async.wait_group 2;\n"); }
        else if (it + 1 < niter) asm volatile("cp.async.wait_group 1;\n");
        else                     asm volatile("cp.async.wait_group 0;\n");
        __syncthreads();

        const int s = it % MM_NST;
        const __nv_bfloat16* sAhi = stg[s];
        const __nv_bfloat16* sAlo = stg[s] + MM_ASZ;
        const __nv_bfloat16* sBhi = stg[s] + 2 * MM_ASZ;
        const __nv_bfloat16* sBlo = stg[s] + 2 * MM_ASZ + MM_BSZ;

        #pragma unroll
        for (int ks = 0; ks < MM_BK; ks += 16) {
            uint32_t bh[4][2], bl[4][2];
            #pragma unroll
            for (int nf = 0; nf < 4; nf++) {
                ldsm_x2t(bh[nf], smem_u32(sBhi + (ks + b_ro) * MM_SB + wn + nf * 8));
                ldsm_x2t(bl[nf], smem_u32(sBlo + (ks + b_ro) * MM_SB + wn + nf * 8));
            }
            #pragma unroll
            for (int mf = 0; mf < 4; mf++) {
                uint32_t ah[4], al[4];
                int arow = wm + mf * 16 + a_ro;
                ldsm_x4(ah, smem_u32(sAhi + arow * MM_SA + ks + a_ko));
                ldsm_x4(al, smem_u32(sAlo + arow * MM_SA + ks + a_ko));
                #pragma unroll
                for (int nf = 0; nf < 4; nf++) {
                    mma16816(acc[mf][nf], ah, bh[nf]);
                    mma16816(acc[mf][nf], ah, bl[nf]);
                    mma16816(acc[mf][nf], al, bh[nf]);
                }
            }
        }
        __syncthreads();
    }

    #pragma unroll
    for (int mf = 0; mf < 4; mf++) {
        int row0 = bm + wm + mf * 16 + (lane >> 2);
        #pragma unroll
        for (int nf = 0; nf < 4; nf++) {
            int col = bn + wn + nf * 8 + (lane & 3) * 2;
            *(float2*)(C + (size_t)row0 * G4 + col) = make_float2(acc[mf][nf][0], acc[mf][nf][1]);
            *(float2*)(C + (size_t)(row0 + 8) * G4 + col) = make_float2(acc[mf][nf][2], acc[mf][nf][3]);
        }
    }
}

// ---------------- split-bf16 pq GEMM (64x64x32, 128 thr) ----------------------
#define P_SA 40
#define P_SB 72
#define P_BM 64
#define P_BN 64
#define P_BK 32
#define P_ASZ (P_BM*P_SA)
#define P_BSZ (P_BK*P_SB)
#define P_STG (2*P_ASZ + 2*P_BSZ)
#define P_SMEM (2*P_STG*2)

__global__ __launch_bounds__(128) void mma_pq_k(
    const __nv_bfloat16* __restrict__ Ahi, const __nv_bfloat16* __restrict__ Alo,
    const __nv_bfloat16* __restrict__ Bhi, const __nv_bfloat16* __restrict__ Blo,
    float* __restrict__ C, const float* __restrict__ bias,
    int M, int N, int K, int lda, int ldb, int ldc)
{
    extern __shared__ __nv_bfloat16 smb[];
    __nv_bfloat16* stg[2] = { smb, smb + P_STG };

    const int tid  = threadIdx.x;
    const int lane = tid & 31, warp = tid >> 5;
    const int bm = blockIdx.y * P_BM, bn = blockIdx.x * P_BN;
    const int wm = (warp >> 1) * 32, wn = (warp & 1) * 32;

    float acc[2][4][4];
    #pragma unroll
    for (int i = 0; i < 2; i++)
        #pragma unroll
        for (int j = 0; j < 4; j++)
            #pragma unroll
            for (int l = 0; l < 4; l++) acc[i][j][l] = 0.f;

    auto issue_loads = [&](int s, int k0) {
        __nv_bfloat16* sAhi = stg[s];
        __nv_bfloat16* sAlo = stg[s] + P_ASZ;
        __nv_bfloat16* sBhi = stg[s] + 2 * P_ASZ;
        __nv_bfloat16* sBlo = stg[s] + 2 * P_ASZ + P_BSZ;
        #pragma unroll
        for (int i = 0; i < 2; i++) {
            int ai = tid * 2 + i, ar = ai >> 2, ac = (ai & 3) * 8;
            CP16(smem_u32(sAhi + ar * P_SA + ac), Ahi + (size_t)(bm + ar) * lda + k0 + ac);
            CP16(smem_u32(sAlo + ar * P_SA + ac), Alo + (size_t)(bm + ar) * lda + k0 + ac);
            int bi = tid * 2 + i, br = bi >> 3, bc = (bi & 7) * 8;
            CP16(smem_u32(sBhi + br * P_SB + bc), Bhi + (size_t)(k0 + br) * ldb + bn + bc);
            CP16(smem_u32(sBlo + br * P_SB + bc), Blo + (size_t)(k0 + br) * ldb + bn + bc);
        }
        asm volatile("cp.async.commit_group;\n");
    };

    const int niter = K / P_BK;
    issue_loads(0, 0);

    const int a_ro = (lane & 7) + ((lane >> 3) & 1) * 8;
    const int a_ko = ((lane >> 4) & 1) * 8;
    const int b_ro = (lane & 7) + ((lane >> 3) & 1) * 8;

    for (int it = 0; it < niter; it++) {
        int s = it & 1;
        if (it + 1 < niter) { issue_loads(s ^ 1, (it + 1) * P_BK);
                              asm volatile("cp.async.wait_group 1;\n"); }
        else                  asm volatile("cp.async.wait_group 0;\n");
        __syncthreads();

        const __nv_bfloat16* sAhi = stg[s];
        const __nv_bfloat16* sAlo = stg[s] + P_ASZ;
        const __nv_bfloat16* sBhi = stg[s] + 2 * P_ASZ;
        const __nv_bfloat16* sBlo = stg[s] + 2 * P_ASZ + P_BSZ;

        #pragma unroll
        for (int ks = 0; ks < P_BK; ks += 16) {
            uint32_t bh[4][2], bl[4][2];
            #pragma unroll
            for (int nf = 0; nf < 4; nf++) {
                ldsm_x2t(bh[nf], smem_u32(sBhi + (ks + b_ro) * P_SB + wn + nf * 8));
                ldsm_x2t(bl[nf], smem_u32(sBlo + (ks + b_ro) * P_SB + wn + nf * 8));
            }
            #pragma unroll
            for (int mf = 0; mf < 2; mf++) {
                uint32_t ah[4], al[4];
                int arow = wm + mf * 16 + a_ro;
                ldsm_x4(ah, smem_u32(sAhi + arow * P_SA + ks + a_ko));
                ldsm_x4(al, smem_u32(sAlo + arow * P_SA + ks + a_ko));
                #pragma unroll
                for (int nf = 0; nf < 4; nf++) {
                    mma16816(acc[mf][nf], ah, bh[nf]);
                    mma16816(acc[mf][nf], ah, bl[nf]);
                    mma16816(acc[mf][nf], al, bh[nf]);
                }
            }
        }
        __syncthreads();
    }

    #pragma unroll
    for (int mf = 0; mf < 2; mf++) {
        int row0 = bm + wm + mf * 16 + (lane >> 2);
        #pragma unroll
        for (int nf = 0; nf < 4; nf++) {
            int col = bn + wn + nf * 8 + (lane & 3) * 2;
            float b0 = bias[col], b1 = bias[col + 1];
            *(float2*)(C + (size_t)row0 * ldc + col) =
                make_float2(acc[mf][nf][0] + b0, acc[mf][nf][1] + b1);
            *(float2*)(C + (size_t)(row0 + 8) * ldc + col) =
                make_float2(acc[mf][nf][2] + b0, acc[mf][nf][3] + b1);
        }
    }
}

// ---------------- flash attend: streamed online softmax -----------------------
#define FA_CH 16
#define FA_NCH (LL/FA_CH)
#define FA_SMEM ((2*FA_CH*EE + EE + LL + FA_CH + FA_CH + 8) * 4)

__global__ __launch_bounds__(256) void attend_flash_k(
    const float* __restrict__ Mg, const int* __restrict__ mask,
    const int* __restrict__ lengths, float* __restrict__ out, int t)
{
    extern __shared__ float smf[];
    float* bufs[2] = { smf, smf + FA_CH * EE };
    float* smPQ   = smf + 2 * FA_CH * EE;
    float* smSall = smPQ + EE;
    float* smS16  = smSall + LL;
    float* smE    = smS16 + FA_CH;
    float* smMisc = smE + FA_CH;

    const int b = blockIdx.x, tid = threadIdx.x;
    const int warp = tid >> 5, lane = tid & 31;

    smPQ[tid] = g_PQ[b * EE + tid];
    const float* gM = Mg + (size_t)b * LL * EE;

    auto issue = [&](int c) {
        float* dst = bufs[c & 1];
        const float* src = gM + c * FA_CH * EE;
        #pragma unroll
        for (int i = 0; i < 4; i++) {
            int ch = tid + i * 256;
            CP16(smem_u32(dst + ch * 4), src + ch * 4);
        }
        asm volatile("cp.async.commit_group;\n");
    };

    issue(0);

    float a = 0.f;
    float m = -1e30f, d = 0.f;

    for (int c = 0; c < FA_NCH; c++) {
        if (c + 1 < FA_NCH) { issue(c + 1); asm volatile("cp.async.wait_group 1;\n"); }
        else                  asm volatile("cp.async.wait_group 0;\n");
        __syncthreads();
        float* smM = bufs[c & 1];

        #pragma unroll
        for (int rr = 0; rr < 2; rr++) {
            int l = rr * 8 + warp;
            float s = 0.f;
            #pragma unroll
            for (int j = 0; j < EE / 32; j++)
                s += smM[l * EE + lane + j * 32] * smPQ[lane + j * 32];
            #pragma unroll
            for (int o = 16; o; o >>= 1) s += __shfl_xor_sync(0xffffffffu, s, o);
            if (lane == 0) {
                int gl = c * FA_CH + l;
                float sv = (mask[b * LL + gl] != 0) ? -1e30f : s;
                smS16[l] = sv;
                smSall[gl] = sv;
            }
        }
        __syncthreads();

        if (warp == 0) {
            float sl = (lane < FA_CH) ? smS16[lane] : -1e30f;
            float mc = sl;
            #pragma unroll
            for (int o = 16; o; o >>= 1) mc = fmaxf(mc, __shfl_xor_sync(0xffffffffu, mc, o));
            float m_new = fmaxf(m, mc);
            float scale = expf(m - m_new);
            float e = (lane < FA_CH) ? expf(sl - m_new) : 0.f;
            float esum = e;
            #pragma unroll
            for (int o = 16; o; o >>= 1) esum += __shfl_xor_sync(0xffffffffu, esum, o);
            d = d * scale + esum;
            m = m_new;
            if (lane < FA_CH) smE[lane] = e;
            if (lane == 0) smMisc[0] = scale;
        }
        __syncthreads();

        float sc = smMisc[0];
        a *= sc;
        #pragma unroll
        for (int l = 0; l < FA_CH; l++)
            a += smE[l] * smM[l * EE + tid];
        __syncthreads();
    }

    if (warp == 0 && lane == 0) { smMisc[1] = m; smMisc[2] = 1.f / d; }
    __syncthreads();
    float m_fin = smMisc[1], inv_d = smMisc[2];

    float app = a * inv_d;
    __nv_bfloat16 h = __float2bfloat16(app);
    g_Xhi[(size_t)b * XW + tid] = h;
    g_Xlo[(size_t)b * XW + tid] = __float2bfloat16(app - __bfloat162float(h));

    if (tid < LL) {
        int len = lengths[b];
        len = min(max(len, 0), TT);
        if (len == t) out[(size_t)b * LL + tid] = expf(smSall[tid] - m_fin) * inv_d;
    }
}

// ---------------- LSTM cell --------------------------------------------------
__global__ void lstm_k(const int* __restrict__ msg, int t)
{
    int idx = blockIdx.x * blockDim.x + threadIdx.x;
    int b = idx >> 9, j = idx & (HH - 1);
    int tok = msg[b * TT + t];
    const float* ga = g_GATT + (size_t)b * G4;
    const float* pe = g_ProjEmb + (size_t)tok * G4;
    float gi = ga[j]          + pe[j]          + g_BiasC[j];
    float gf = ga[HH + j]     + pe[HH + j]     + g_BiasC[HH + j];
    float gg = ga[2 * HH + j] + pe[2 * HH + j] + g_BiasC[2 * HH + j];
    float go = ga[3 * HH + j] + pe[3 * HH + j] + g_BiasC[3 * HH + j];
    float c  = g_C[idx];
    float si = 1.f / (1.f + expf(-gi));
    float sf = 1.f / (1.f + expf(-gf));
    float so = 1.f / (1.f + expf(-go));
    float cn = sf * c + si * tanhf(gg);
    float hn = so * tanhf(cn);
    g_C[idx] = cn;
    __nv_bfloat16 hb = __float2bfloat16(hn);
    g_Xhi[(size_t)b * XW + EE + j] = hb;
    g_Xlo[(size_t)b * XW + EE + j] = __float2bfloat16(hn - __bfloat162float(hb));
}

// ---------------- driver -----------------------------------------------------
extern "C" void kernel_launch(void* const* d_in, const int* in_sizes, int n_in,
                              void* d_out, int out_size)
{
    const int*   msg     = (const int*)d_in[0];
    const float* Mg      = (const float*)d_in[1];
    const int*   mask    = (const int*)d_in[2];
    const int*   lengths = (const int*)d_in[3];
    const float* emb     = (const float*)d_in[4];
    const float* Wq      = (const float*)d_in[5];
    const float* bq      = (const float*)d_in[6];
    const float* Wc      = (const float*)d_in[7];
    const float* bc      = (const float*)d_in[8];
    const float* W_ih    = (const float*)d_in[9];
    const float* W_hh    = (const float*)d_in[10];
    const float* b_ih    = (const float*)d_in[11];
    const float* b_hh    = (const float*)d_in[12];
    float* out = (float*)d_out;
    int Vp1 = in_sizes[4] / EE;
    if (Vp1 > VMAX) Vp1 = VMAX;
    int ntail = out_size - BSZ * LL;
    if (ntail < 0) ntail = 0;

    float *pPQ, *pGATT, *pPE;
    __nv_bfloat16 *pXhi, *pXlo, *pWhi, *pWlo, *pWqThi, *pWqTlo;
    cudaGetSymbolAddress((void**)&pPQ,    g_PQ);
    cudaGetSymbolAddress((void**)&pGATT,  g_GATT);
    cudaGetSymbolAddress((void**)&pPE,    g_ProjEmb);
    cudaGetSymbolAddress((void**)&pXhi,   g_Xhi);
    cudaGetSymbolAddress((void**)&pXlo,   g_Xlo);
    cudaGetSymbolAddress((void**)&pWhi,   g_Whi);
    cudaGetSymbolAddress((void**)&pWlo,   g_Wlo);
    cudaGetSymbolAddress((void**)&pWqThi, g_WqThi);
    cudaGetSymbolAddress((void**)&pWqTlo, g_WqTlo);

    cudaFuncSetAttribute(attend_flash_k, cudaFuncAttributeMaxDynamicSharedMemorySize, FA_SMEM);
    cudaFuncSetAttribute(mma_gemm_k, cudaFuncAttributeMaxDynamicSharedMemorySize, MM_SMEM);
    cudaFuncSetAttribute(mma_pq_k,   cudaFuncAttributeMaxDynamicSharedMemorySize, P_SMEM);

    // launch 0: transposes + biascomb + init + zerotail
    prep_k<<<dim3(24, 64, 5), dim3(32, 8)>>>(Wq, W_ih, Wc, W_hh,
                                             b_ih, b_hh, bc, bq, out, ntail);
    // launch 1: setup GEMMs (Wcomb->split, ProjEmb) + WqT split
    gemm2_k<<<dim3(32, 16, 3), 256>>>(emb, Vp1);

    // launch 2: attend(0); launch 3: gates(0)  <- ncu -s 5 captures my index 3
    for (int t = 0; t < TT; t++) {
        attend_flash_k<<<BSZ, 256, FA_SMEM>>>(Mg, mask, lengths, out, t);
        mma_gemm_k<<<dim3(G4 / MM_BN, BSZ / MM_BM), 256, MM_SMEM>>>(
            pXhi, pXlo, pWhi, pWlo, pGATT);
        lstm_k<<<(BSZ * HH) / 256, 256>>>(msg, t);
        mma_pq_k<<<dim3(EE / P_BN, BSZ / P_BM), 128, P_SMEM>>>(
            pXhi + EE, pXlo + EE, pWqThi, pWqTlo, pPQ, bq,
            BSZ, EE, HH, XW, EE, EE);
    }
    attend_flash_k<<<BSZ, 256, FA_SMEM>>>(Mg, mask, lengths, out, TT);
}

// round 9
// speedup vs baseline: 1.1770x; 1.0235x over previous
#include <cuda_runtime.h>
#include <cuda_bf16.h>
#include <math.h>
#include <stdint.h>

#define BSZ 1024
#define LL  128
#define EE  256
#define HH  512
#define TT  20
#define G4  (4*HH)    // 2048
#define XW  (EE+HH)   // 768
#define VMAX 1024

// ---------------- persistent scratch ----------------------------------------
__device__ float g_C[BSZ*HH];
__device__ float g_PQ[BSZ*EE];
__device__ float g_GATT[BSZ*G4];
__device__ float g_WqT[HH*EE];
__device__ float g_WihT[EE*G4];
__device__ float g_WcT[XW*HH];
__device__ float g_WhhT[HH*G4];
__device__ float g_ProjEmb[VMAX*G4];
__device__ float g_BiasC[G4];
__device__ __nv_bfloat16 g_Xhi[BSZ*XW];    // [applied | h] split-bf16
__device__ __nv_bfloat16 g_Xlo[BSZ*XW];
__device__ __nv_bfloat16 g_Whi[XW*G4];     // Wcomb split, [K,N]
__device__ __nv_bfloat16 g_Wlo[XW*G4];
__device__ __nv_bfloat16 g_WqThi[HH*EE];
__device__ __nv_bfloat16 g_WqTlo[HH*EE];

__device__ __forceinline__ uint32_t smem_u32(const void* p) {
    return (uint32_t)__cvta_generic_to_shared(p);
}
#define CP16(dst, src) asm volatile("cp.async.cg.shared.global [%0], [%1], 16;\n" :: "r"(dst), "l"(src))

// ---------------- prep: 4 transposes + biascomb + init + zerotail (1 launch) --
__device__ __forceinline__ void transpose_dev(const float* __restrict__ in,
                                              float* __restrict__ out,
                                              int rows, int cols)
{
    __shared__ float tile[32][33];
    int x0 = blockIdx.x * 32, y0 = blockIdx.y * 32;
    if (x0 >= cols || y0 >= rows) return;
    int tx = threadIdx.x;
    for (int j = threadIdx.y; j < 32; j += 8) {
        int r = y0 + j, c = x0 + tx;
        if (r < rows && c < cols) tile[j][tx] = in[(size_t)r * cols + c];
    }
    __syncthreads();
    for (int j = threadIdx.y; j < 32; j += 8) {
        int orow = x0 + j, ocol = y0 + tx;
        if (orow < cols && ocol < rows) out[(size_t)orow * rows + ocol] = tile[tx][j];
    }
}

__global__ void prep_k(const float* __restrict__ Wq, const float* __restrict__ W_ih,
                       const float* __restrict__ Wc, const float* __restrict__ W_hh,
                       const float* __restrict__ b_ih, const float* __restrict__ b_hh,
                       const float* __restrict__ bc, const float* __restrict__ bq,
                       float* __restrict__ out, int ntail)
{
    int z = blockIdx.z;
    if (z == 0)      { transpose_dev(Wq,   g_WqT,  EE, HH); return; }
    else if (z == 1) { transpose_dev(W_ih, g_WihT, G4, EE); return; }
    else if (z == 2) { transpose_dev(Wc,   g_WcT,  HH, XW); return; }
    else if (z == 3) { transpose_dev(W_hh, g_WhhT, G4, HH); return; }

    const int tid  = threadIdx.y * 32 + threadIdx.x;
    const int lane = tid & 31, warp = tid >> 5;
    const int nb   = gridDim.x * gridDim.y;
    const int bid  = blockIdx.y * gridDim.x + blockIdx.x;

    for (int j = bid * 8 + warp; j < G4; j += nb * 8) {
        float s = 0.f;
        for (int h = lane; h < HH; h += 32) s += bc[h] * W_hh[(size_t)j * HH + h];
        #pragma unroll
        for (int o = 16; o; o >>= 1) s += __shfl_xor_sync(0xffffffffu, s, o);
        if (lane == 0) g_BiasC[j] = b_ih[j] + b_hh[j] + s;
    }
    for (int i = bid * 256 + tid; i < BSZ * HH; i += nb * 256) {
        g_C[i] = 0.f;
        int b = i >> 9, j = i & (HH - 1);
        g_Xhi[(size_t)b * XW + EE + j] = __float2bfloat16(0.f);
        g_Xlo[(size_t)b * XW + EE + j] = __float2bfloat16(0.f);
    }
    for (int i = bid * 256 + tid; i < BSZ * EE; i += nb * 256)
        g_PQ[i] = bq[i & (EE - 1)];
    for (int i = bid * 256 + tid; i < ntail; i += nb * 256)
        out[BSZ * LL + i] = 0.f;
}

// ---------------- setup GEMMs (1 launch, z-sliced) ----------------------------
__device__ __forceinline__ void gemm_dev(
    const float* __restrict__ A, const float* __restrict__ B,
    float* __restrict__ C, __nv_bfloat16* __restrict__ Chi,
    __nv_bfloat16* __restrict__ Clo,
    int M, int N, int K, int lda, int ldb, int ldc, int mode)
{
    __shared__ float As[16][68];
    __shared__ float Bs[16][68];
    const int tid = threadIdx.x;
    const int tx  = tid & 15, ty = tid >> 4;
    const int bm  = blockIdx.y << 6, bn = blockIdx.x << 6;
    const int arow = tid >> 2, ak = (tid & 3) << 2;
    const int brow = tid >> 4, bcol = (tid & 15) << 2;

    float acc[4][4];
    #pragma unroll
    for (int i = 0; i < 4; i++)
        #pragma unroll
        for (int j = 0; j < 4; j++) acc[i][j] = 0.f;

    const bool aval = (bm + arow) < M;
    const float* Aptr = A + (size_t)(bm + arow) * lda + ak;
    const float* Bptr = B + (size_t)brow * ldb + bn + bcol;

    for (int k0 = 0; k0 < K; k0 += 16) {
        float4 av = aval ? *(const float4*)(Aptr + k0)
                         : make_float4(0.f, 0.f, 0.f, 0.f);
        As[ak + 0][arow] = av.x; As[ak + 1][arow] = av.y;
        As[ak + 2][arow] = av.z; As[ak + 3][arow] = av.w;
        float4 bv = *(const float4*)(Bptr + (size_t)k0 * ldb);
        *(float4*)(&Bs[brow][bcol]) = bv;
        __syncthreads();
        #pragma unroll
        for (int k = 0; k < 16; k++) {
            float4 a = *(const float4*)(&As[k][ty << 2]);
            float4 b = *(const float4*)(&Bs[k][tx << 2]);
            acc[0][0] += a.x * b.x; acc[0][1] += a.x * b.y; acc[0][2] += a.x * b.z; acc[0][3] += a.x * b.w;
            acc[1][0] += a.y * b.x; acc[1][1] += a.y * b.y; acc[1][2] += a.y * b.z; acc[1][3] += a.y * b.w;
            acc[2][0] += a.z * b.x; acc[2][1] += a.z * b.y; acc[2][2] += a.z * b.z; acc[2][3] += a.z * b.w;
            acc[3][0] += a.w * b.x; acc[3][1] += a.w * b.y; acc[3][2] += a.w * b.z; acc[3][3] += a.w * b.w;
        }
        __syncthreads();
    }

    #pragma unroll
    for (int i = 0; i < 4; i++) {
        int row = bm + (ty << 2) + i;
        if (row < M) {
            if (mode == 0) {
                *(float4*)(C + (size_t)row * ldc + bn + (tx << 2)) =
                    make_float4(acc[i][0], acc[i][1], acc[i][2], acc[i][3]);
            } else {
                #pragma unroll
                for (int q = 0; q < 4; q++) {
                    float o = acc[i][q];
                    __nv_bfloat16 h = __float2bfloat16(o);
                    size_t off = (size_t)row * ldc + bn + (tx << 2) + q;
                    Chi[off] = h;
                    Clo[off] = __float2bfloat16(o - __bfloat162float(h));
                }
            }
        }
    }
}

__global__ __launch_bounds__(256) void gemm2_k(const float* __restrict__ emb, int Vp1)
{
    int z = blockIdx.z;
    if (z == 0) {
        if (blockIdx.y < 12)
            gemm_dev(g_WcT, g_WhhT, nullptr, g_Whi, g_Wlo,
                     XW, G4, HH, HH, G4, G4, 1);
    } else if (z == 1) {
        gemm_dev(emb, g_WihT, g_ProjEmb, nullptr, nullptr,
                 Vp1, G4, EE, EE, G4, G4, 0);
    } else {
        int bid = blockIdx.y * gridDim.x + blockIdx.x;
        int i = bid * 256 + threadIdx.x;
        if (i < HH * EE) {
            float x = g_WqT[i];
            __nv_bfloat16 h = __float2bfloat16(x);
            g_WqThi[i] = h;
            g_WqTlo[i] = __float2bfloat16(x - __bfloat162float(h));
        }
    }
}

// ---------------- MMA helpers --------------------------------------------------
__device__ __forceinline__ void ldsm_x4(uint32_t r[4], uint32_t addr) {
    asm volatile("ldmatrix.sync.aligned.m8n8.x4.shared.b16 {%0,%1,%2,%3}, [%4];\n"
        : "=r"(r[0]), "=r"(r[1]), "=r"(r[2]), "=r"(r[3]) : "r"(addr));
}
__device__ __forceinline__ void ldsm_x2t(uint32_t r[2], uint32_t addr) {
    asm volatile("ldmatrix.sync.aligned.m8n8.x2.trans.shared.b16 {%0,%1}, [%2];\n"
        : "=r"(r[0]), "=r"(r[1]) : "r"(addr));
}
__device__ __forceinline__ void mma16816(float* c, const uint32_t a[4], const uint32_t b[2]) {
    asm volatile(
        "mma.sync.aligned.m16n8k16.row.col.f32.bf16.bf16.f32 "
        "{%0,%1,%2,%3}, {%4,%5,%6,%7}, {%8,%9}, {%0,%1,%2,%3};\n"
        : "+f"(c[0]), "+f"(c[1]), "+f"(c[2]), "+f"(c[3])
        : "r"(a[0]), "r"(a[1]), "r"(a[2]), "r"(a[3]), "r"(b[0]), "r"(b[1]));
}

// ---------------- gates GEMM (128x128x32, 16 warps, 3-stage) ------------------
#define MM_SA 40
#define MM_SB 136
#define MM_BM 128
#define MM_BN 128
#define MM_BK 32
#define MM_ASZ (MM_BM*MM_SA)
#define MM_BSZ (MM_BK*MM_SB)
#define MM_STG (2*MM_ASZ + 2*MM_BSZ)   // 18944 elems
#define MM_NST 3
#define MM_SMEM (MM_NST*MM_STG*2)      // 113664 B

__global__ __launch_bounds__(512, 1) void mma_gemm_k(
    const __nv_bfloat16* __restrict__ Ahi, const __nv_bfloat16* __restrict__ Alo,
    const __nv_bfloat16* __restrict__ Bhi, const __nv_bfloat16* __restrict__ Blo,
    float* __restrict__ C)
{
    extern __shared__ __nv_bfloat16 sm[];
    __nv_bfloat16* stg[MM_NST] = { sm, sm + MM_STG, sm + 2 * MM_STG };

    const int tid  = threadIdx.x;
    const int lane = tid & 31, warp = tid >> 5;
    const int bm = blockIdx.y * MM_BM, bn = blockIdx.x * MM_BN;
    const int wm = (warp >> 2) * 32, wn = (warp & 3) * 32;   // 32x32 warp tile

    float acc[2][4][4];
    #pragma unroll
    for (int i = 0; i < 2; i++)
        #pragma unroll
        for (int j = 0; j < 4; j++)
            #pragma unroll
            for (int l = 0; l < 4; l++) acc[i][j][l] = 0.f;

    auto issue_loads = [&](int s, int k0) {
        __nv_bfloat16* sAhi = stg[s];
        __nv_bfloat16* sAlo = stg[s] + MM_ASZ;
        __nv_bfloat16* sBhi = stg[s] + 2 * MM_ASZ;
        __nv_bfloat16* sBlo = stg[s] + 2 * MM_ASZ + MM_BSZ;
        // 512 chunks per array, 512 threads: 1 chunk each
        int ar = tid >> 2, ac = (tid & 3) * 8;
        CP16(smem_u32(sAhi + ar * MM_SA + ac), Ahi + (size_t)(bm + ar) * XW + k0 + ac);
        CP16(smem_u32(sAlo + ar * MM_SA + ac), Alo + (size_t)(bm + ar) * XW + k0 + ac);
        int br = tid >> 4, bc = (tid & 15) * 8;
        CP16(smem_u32(sBhi + br * MM_SB + bc), Bhi + (size_t)(k0 + br) * G4 + bn + bc);
        CP16(smem_u32(sBlo + br * MM_SB + bc), Blo + (size_t)(k0 + br) * G4 + bn + bc);
        asm volatile("cp.async.commit_group;\n");
    };

    const int niter = XW / MM_BK;   // 24
    issue_loads(0, 0);
    issue_loads(1, MM_BK);

    const int a_ro = (lane & 7) + ((lane >> 3) & 1) * 8;
    const int a_ko = ((lane >> 4) & 1) * 8;
    const int b_ro = (lane & 7) + ((lane >> 3) & 1) * 8;

    for (int it = 0; it < niter; it++) {
        if (it + 2 < niter) { issue_loads((it + 2) % MM_NST, (it + 2) * MM_BK);
                              asm volatile("cp.async.wait_group 2;\n"); }
        else if (it + 1 < niter) asm volatile("cp.async.wait_group 1;\n");
        else                     asm volatile("cp.async.wait_group 0;\n");
        __syncthreads();

        const int s = it % MM_NST;
        const __nv_bfloat16* sAhi = stg[s];
        const __nv_bfloat16* sAlo = stg[s] + MM_ASZ;
        const __nv_bfloat16* sBhi = stg[s] + 2 * MM_ASZ;
        const __nv_bfloat16* sBlo = stg[s] + 2 * MM_ASZ + MM_BSZ;

        #pragma unroll
        for (int ks = 0; ks < MM_BK; ks += 16) {
            uint32_t bh[4][2], bl[4][2];
            #pragma unroll
            for (int nf = 0; nf < 4; nf++) {
                ldsm_x2t(bh[nf], smem_u32(sBhi + (ks + b_ro) * MM_SB + wn + nf * 8));
                ldsm_x2t(bl[nf], smem_u32(sBlo + (ks + b_ro) * MM_SB + wn + nf * 8));
            }
            #pragma unroll
            for (int mf = 0; mf < 2; mf++) {
                uint32_t ah[4], al[4];
                int arow = wm + mf * 16 + a_ro;
                ldsm_x4(ah, smem_u32(sAhi + arow * MM_SA + ks + a_ko));
                ldsm_x4(al, smem_u32(sAlo + arow * MM_SA + ks + a_ko));
                #pragma unroll
                for (int nf = 0; nf < 4; nf++) {
                    mma16816(acc[mf][nf], ah, bh[nf]);
                    mma16816(acc[mf][nf], ah, bl[nf]);
                    mma16816(acc[mf][nf], al, bh[nf]);
                }
            }
        }
        __syncthreads();
    }

    #pragma unroll
    for (int mf = 0; mf < 2; mf++) {
        int row0 = bm + wm + mf * 16 + (lane >> 2);
        #pragma unroll
        for (int nf = 0; nf < 4; nf++) {
            int col = bn + wn + nf * 8 + (lane & 3) * 2;
            *(float2*)(C + (size_t)row0 * G4 + col) = make_float2(acc[mf][nf][0], acc[mf][nf][1]);
            *(float2*)(C + (size_t)(row0 + 8) * G4 + col) = make_float2(acc[mf][nf][2], acc[mf][nf][3]);
        }
    }
}

// ---------------- split-bf16 pq GEMM (64x64x32, 128 thr) ----------------------
#define P_SA 40
#define P_SB 72
#define P_BM 64
#define P_BN 64
#define P_BK 32
#define P_ASZ (P_BM*P_SA)
#define P_BSZ (P_BK*P_SB)
#define P_STG (2*P_ASZ + 2*P_BSZ)
#define P_SMEM (2*P_STG*2)

__global__ __launch_bounds__(128) void mma_pq_k(
    const __nv_bfloat16* __restrict__ Ahi, const __nv_bfloat16* __restrict__ Alo,
    const __nv_bfloat16* __restrict__ Bhi, const __nv_bfloat16* __restrict__ Blo,
    float* __restrict__ C, const float* __restrict__ bias,
    int M, int N, int K, int lda, int ldb, int ldc)
{
    extern __shared__ __nv_bfloat16 smb[];
    __nv_bfloat16* stg[2] = { smb, smb + P_STG };

    const int tid  = threadIdx.x;
    const int lane = tid & 31, warp = tid >> 5;
    const int bm = blockIdx.y * P_BM, bn = blockIdx.x * P_BN;
    const int wm = (warp >> 1) * 32, wn = (warp & 1) * 32;

    float acc[2][4][4];
    #pragma unroll
    for (int i = 0; i < 2; i++)
        #pragma unroll
        for (int j = 0; j < 4; j++)
            #pragma unroll
            for (int l = 0; l < 4; l++) acc[i][j][l] = 0.f;

    auto issue_loads = [&](int s, int k0) {
        __nv_bfloat16* sAhi = stg[s];
        __nv_bfloat16* sAlo = stg[s] + P_ASZ;
        __nv_bfloat16* sBhi = stg[s] + 2 * P_ASZ;
        __nv_bfloat16* sBlo = stg[s] + 2 * P_ASZ + P_BSZ;
        #pragma unroll
        for (int i = 0; i < 2; i++) {
            int ai = tid * 2 + i, ar = ai >> 2, ac = (ai & 3) * 8;
            CP16(smem_u32(sAhi + ar * P_SA + ac), Ahi + (size_t)(bm + ar) * lda + k0 + ac);
            CP16(smem_u32(sAlo + ar * P_SA + ac), Alo + (size_t)(bm + ar) * lda + k0 + ac);
            int bi = tid * 2 + i, br = bi >> 3, bc = (bi & 7) * 8;
            CP16(smem_u32(sBhi + br * P_SB + bc), Bhi + (size_t)(k0 + br) * ldb + bn + bc);
            CP16(smem_u32(sBlo + br * P_SB + bc), Blo + (size_t)(k0 + br) * ldb + bn + bc);
        }
        asm volatile("cp.async.commit_group;\n");
    };

    const int niter = K / P_BK;
    issue_loads(0, 0);

    const int a_ro = (lane & 7) + ((lane >> 3) & 1) * 8;
    const int a_ko = ((lane >> 4) & 1) * 8;
    const int b_ro = (lane & 7) + ((lane >> 3) & 1) * 8;

    for (int it = 0; it < niter; it++) {
        int s = it & 1;
        if (it + 1 < niter) { issue_loads(s ^ 1, (it + 1) * P_BK);
                              asm volatile("cp.async.wait_group 1;\n"); }
        else                  asm volatile("cp.async.wait_group 0;\n");
        __syncthreads();

        const __nv_bfloat16* sAhi = stg[s];
        const __nv_bfloat16* sAlo = stg[s] + P_ASZ;
        const __nv_bfloat16* sBhi = stg[s] + 2 * P_ASZ;
        const __nv_bfloat16* sBlo = stg[s] + 2 * P_ASZ + P_BSZ;

        #pragma unroll
        for (int ks = 0; ks < P_BK; ks += 16) {
            uint32_t bh[4][2], bl[4][2];
            #pragma unroll
            for (int nf = 0; nf < 4; nf++) {
                ldsm_x2t(bh[nf], smem_u32(sBhi + (ks + b_ro) * P_SB + wn + nf * 8));
                ldsm_x2t(bl[nf], smem_u32(sBlo + (ks + b_ro) * P_SB + wn + nf * 8));
            }
            #pragma unroll
            for (int mf = 0; mf < 2; mf++) {
                uint32_t ah[4], al[4];
                int arow = wm + mf * 16 + a_ro;
                ldsm_x4(ah, smem_u32(sAhi + arow * P_SA + ks + a_ko));
                ldsm_x4(al, smem_u32(sAlo + arow * P_SA + ks + a_ko));
                #pragma unroll
                for (int nf = 0; nf < 4; nf++) {
                    mma16816(acc[mf][nf], ah, bh[nf]);
                    mma16816(acc[mf][nf], ah, bl[nf]);
                    mma16816(acc[mf][nf], al, bh[nf]);
                }
            }
        }
        __syncthreads();
    }

    #pragma unroll
    for (int mf = 0; mf < 2; mf++) {
        int row0 = bm + wm + mf * 16 + (lane >> 2);
        #pragma unroll
        for (int nf = 0; nf < 4; nf++) {
            int col = bn + wn + nf * 8 + (lane & 3) * 2;
            float b0 = bias[col], b1 = bias[col + 1];
            *(float2*)(C + (size_t)row0 * ldc + col) =
                make_float2(acc[mf][nf][0] + b0, acc[mf][nf][1] + b1);
            *(float2*)(C + (size_t)(row0 + 8) * ldc + col) =
                make_float2(acc[mf][nf][2] + b0, acc[mf][nf][3] + b1);
        }
    }
}

// ---------------- flash attend: streamed online softmax -----------------------
#define FA_CH 16
#define FA_NCH (LL/FA_CH)
#define FA_SMEM ((2*FA_CH*EE + EE + LL + FA_CH + FA_CH + 8) * 4)

__global__ __launch_bounds__(256) void attend_flash_k(
    const float* __restrict__ Mg, const int* __restrict__ mask,
    const int* __restrict__ lengths, float* __restrict__ out, int t)
{
    extern __shared__ float smf[];
    float* bufs[2] = { smf, smf + FA_CH * EE };
    float* smPQ   = smf + 2 * FA_CH * EE;
    float* smSall = smPQ + EE;
    float* smS16  = smSall + LL;
    float* smE    = smS16 + FA_CH;
    float* smMisc = smE + FA_CH;

    const int b = blockIdx.x, tid = threadIdx.x;
    const int warp = tid >> 5, lane = tid & 31;

    smPQ[tid] = g_PQ[b * EE + tid];
    const float* gM = Mg + (size_t)b * LL * EE;

    auto issue = [&](int c) {
        float* dst = bufs[c & 1];
        const float* src = gM + c * FA_CH * EE;
        #pragma unroll
        for (int i = 0; i < 4; i++) {
            int ch = tid + i * 256;
            CP16(smem_u32(dst + ch * 4), src + ch * 4);
        }
        asm volatile("cp.async.commit_group;\n");
    };

    issue(0);

    float a = 0.f;
    float m = -1e30f, d = 0.f;

    for (int c = 0; c < FA_NCH; c++) {
        if (c + 1 < FA_NCH) { issue(c + 1); asm volatile("cp.async.wait_group 1;\n"); }
        else                  asm volatile("cp.async.wait_group 0;\n");
        __syncthreads();
        float* smM = bufs[c & 1];

        #pragma unroll
        for (int rr = 0; rr < 2; rr++) {
            int l = rr * 8 + warp;
            float s = 0.f;
            #pragma unroll
            for (int j = 0; j < EE / 32; j++)
                s += smM[l * EE + lane + j * 32] * smPQ[lane + j * 32];
            #pragma unroll
            for (int o = 16; o; o >>= 1) s += __shfl_xor_sync(0xffffffffu, s, o);
            if (lane == 0) {
                int gl = c * FA_CH + l;
                float sv = (mask[b * LL + gl] != 0) ? -1e30f : s;
                smS16[l] = sv;
                smSall[gl] = sv;
            }
        }
        __syncthreads();

        if (warp == 0) {
            float sl = (lane < FA_CH) ? smS16[lane] : -1e30f;
            float mc = sl;
            #pragma unroll
            for (int o = 16; o; o >>= 1) mc = fmaxf(mc, __shfl_xor_sync(0xffffffffu, mc, o));
            float m_new = fmaxf(m, mc);
            float scale = expf(m - m_new);
            float e = (lane < FA_CH) ? expf(sl - m_new) : 0.f;
            float esum = e;
            #pragma unroll
            for (int o = 16; o; o >>= 1) esum += __shfl_xor_sync(0xffffffffu, esum, o);
            d = d * scale + esum;
            m = m_new;
            if (lane < FA_CH) smE[lane] = e;
            if (lane == 0) smMisc[0] = scale;
        }
        __syncthreads();

        float sc = smMisc[0];
        a *= sc;
        #pragma unroll
        for (int l = 0; l < FA_CH; l++)
            a += smE[l] * smM[l * EE + tid];
        __syncthreads();
    }

    if (warp == 0 && lane == 0) { smMisc[1] = m; smMisc[2] = 1.f / d; }
    __syncthreads();
    float m_fin = smMisc[1], inv_d = smMisc[2];

    float app = a * inv_d;
    __nv_bfloat16 h = __float2bfloat16(app);
    g_Xhi[(size_t)b * XW + tid] = h;
    g_Xlo[(size_t)b * XW + tid] = __float2bfloat16(app - __bfloat162float(h));

    if (tid < LL) {
        int len = lengths[b];
        len = min(max(len, 0), TT);
        if (len == t) out[(size_t)b * LL + tid] = expf(smSall[tid] - m_fin) * inv_d;
    }
}

// ---------------- LSTM cell --------------------------------------------------
__global__ void lstm_k(const int* __restrict__ msg, int t)
{
    int idx = blockIdx.x * blockDim.x + threadIdx.x;
    int b = idx >> 9, j = idx & (HH - 1);
    int tok = msg[b * TT + t];
    const float* ga = g_GATT + (size_t)b * G4;
    const float* pe = g_ProjEmb + (size_t)tok * G4;
    float gi = ga[j]          + pe[j]          + g_BiasC[j];
    float gf = ga[HH + j]     + pe[HH + j]     + g_BiasC[HH + j];
    float gg = ga[2 * HH + j] + pe[2 * HH + j] + g_BiasC[2 * HH + j];
    float go = ga[3 * HH + j] + pe[3 * HH + j] + g_BiasC[3 * HH + j];
    float c  = g_C[idx];
    float si = 1.f / (1.f + expf(-gi));
    float sf = 1.f / (1.f + expf(-gf));
    float so = 1.f / (1.f + expf(-go));
    float cn = sf * c + si * tanhf(gg);
    float hn = so * tanhf(cn);
    g_C[idx] = cn;
    __nv_bfloat16 hb = __float2bfloat16(hn);
    g_Xhi[(size_t)b * XW + EE + j] = hb;
    g_Xlo[(size_t)b * XW + EE + j] = __float2bfloat16(hn - __bfloat162float(hb));
}

// ---------------- driver -----------------------------------------------------
extern "C" void kernel_launch(void* const* d_in, const int* in_sizes, int n_in,
                              void* d_out, int out_size)
{
    const int*   msg     = (const int*)d_in[0];
    const float* Mg      = (const float*)d_in[1];
    const int*   mask    = (const int*)d_in[2];
    const int*   lengths = (const int*)d_in[3];
    const float* emb     = (const float*)d_in[4];
    const float* Wq      = (const float*)d_in[5];
    const float* bq      = (const float*)d_in[6];
    const float* Wc      = (const float*)d_in[7];
    const float* bc      = (const float*)d_in[8];
    const float* W_ih    = (const float*)d_in[9];
    const float* W_hh    = (const float*)d_in[10];
    const float* b_ih    = (const float*)d_in[11];
    const float* b_hh    = (const float*)d_in[12];
    float* out = (float*)d_out;
    int Vp1 = in_sizes[4] / EE;
    if (Vp1 > VMAX) Vp1 = VMAX;
    int ntail = out_size - BSZ * LL;
    if (ntail < 0) ntail = 0;

    float *pPQ, *pGATT;
    __nv_bfloat16 *pXhi, *pXlo, *pWhi, *pWlo, *pWqThi, *pWqTlo;
    cudaGetSymbolAddress((void**)&pPQ,    g_PQ);
    cudaGetSymbolAddress((void**)&pGATT,  g_GATT);
    cudaGetSymbolAddress((void**)&pXhi,   g_Xhi);
    cudaGetSymbolAddress((void**)&pXlo,   g_Xlo);
    cudaGetSymbolAddress((void**)&pWhi,   g_Whi);
    cudaGetSymbolAddress((void**)&pWlo,   g_Wlo);
    cudaGetSymbolAddress((void**)&pWqThi, g_WqThi);
    cudaGetSymbolAddress((void**)&pWqTlo, g_WqTlo);

    cudaFuncSetAttribute(attend_flash_k, cudaFuncAttributeMaxDynamicSharedMemorySize, FA_SMEM);
    cudaFuncSetAttribute(mma_gemm_k, cudaFuncAttributeMaxDynamicSharedMemorySize, MM_SMEM);
    cudaFuncSetAttribute(mma_pq_k,   cudaFuncAttributeMaxDynamicSharedMemorySize, P_SMEM);

    prep_k<<<dim3(24, 64, 5), dim3(32, 8)>>>(Wq, W_ih, Wc, W_hh,
                                             b_ih, b_hh, bc, bq, out, ntail);
    gemm2_k<<<dim3(32, 16, 3), 256>>>(emb, Vp1);

    // launch 2: attend(0); launch 3: gates(0)  <- ncu -s 5 captures my index 3
    for (int t = 0; t < TT; t++) {
        attend_flash_k<<<BSZ, 256, FA_SMEM>>>(Mg, mask, lengths, out, t);
        mma_gemm_k<<<dim3(G4 / MM_BN, BSZ / MM_BM), 512, MM_SMEM>>>(
            pXhi, pXlo, pWhi, pWlo, pGATT);
        lstm_k<<<(BSZ * HH) / 256, 256>>>(msg, t);
        mma_pq_k<<<dim3(EE / P_BN, BSZ / P_BM), 128, P_SMEM>>>(
            pXhi + EE, pXlo + EE, pWqThi, pWqTlo, pPQ, bq,
            BSZ, EE, HH, XW, EE, EE);
    }
    attend_flash_k<<<BSZ, 256, FA_SMEM>>>(Mg, mask, lengths, out, TT);
}